// round 1
// baseline (speedup 1.0000x reference)
#include <cuda_runtime.h>
#include <cuda_bf16.h>
#include <math.h>

// Problem constants
#define DIM_  2048
#define SEQ_  2048
#define BAT_  2
#define HEADS_ 16
#define HD_   128
#define CTX_  512
#define FFN_  8192
#define NROWS (BAT_*SEQ_)    // 4096
#define CROWS (BAT_*CTX_)    // 1024
#define EPS_  1e-6f

// ---------------- scratch (static device globals; no allocation) ----------
__device__ float g_xn[NROWS*DIM_];
__device__ float g_q [NROWS*DIM_];
__device__ float g_k [NROWS*DIM_];
__device__ float g_v [NROWS*DIM_];
__device__ float g_y [NROWS*DIM_];
__device__ float g_ck[CROWS*DIM_];
__device__ float g_cv[CROWS*DIM_];
__device__ float g_h [(size_t)NROWS*FFN_];
__device__ float g_em[BAT_*6*DIM_];

// ---------------- small helpers -------------------------------------------
__device__ __forceinline__ float gelu_tanh(float v) {
    const float c = 0.7978845608028654f;
    float t = c * (v + 0.044715f * v * v * v);
    return 0.5f * v * (1.0f + tanhf(t));
}

// ---------------- em = modulation + e --------------------------------------
__global__ void em_kernel(const float* __restrict__ e, const float* __restrict__ mod) {
    int i = blockIdx.x * 256 + threadIdx.x;
    if (i < BAT_*6*DIM_) {
        g_em[i] = e[i] + mod[i % (6*DIM_)];
    }
}

// ---------------- LayerNorm (optionally modulated / affine) ----------------
// y = ln(x) * (add_one + scale[b*ss + c]) + shift[b*hs + c]
__global__ __launch_bounds__(256) void ln_kernel(
    const float* __restrict__ X, float* __restrict__ Yout,
    const float* __restrict__ scale, int sstride,
    const float* __restrict__ shift, int hstride,
    float add_one, int rows_per_batch)
{
    int row = blockIdx.x;
    const float* xr = X + (size_t)row * DIM_;
    int t = threadIdx.x;
    float s = 0.f, s2 = 0.f;
    float vbuf[8];
#pragma unroll
    for (int i = 0; i < 8; i++) {
        float v = xr[t + 256*i];
        vbuf[i] = v;
        s += v; s2 += v*v;
    }
    __shared__ float r1[8], r2[8];
    unsigned lane = t & 31, warp = t >> 5;
#pragma unroll
    for (int o = 16; o; o >>= 1) {
        s  += __shfl_xor_sync(~0u, s,  o);
        s2 += __shfl_xor_sync(~0u, s2, o);
    }
    if (lane == 0) { r1[warp] = s; r2[warp] = s2; }
    __syncthreads();
    if (t == 0) {
        float a = 0.f, b = 0.f;
#pragma unroll
        for (int i = 0; i < 8; i++) { a += r1[i]; b += r2[i]; }
        r1[0] = a; r2[0] = b;
    }
    __syncthreads();
    float mean = r1[0] * (1.0f/DIM_);
    float var  = r2[0] * (1.0f/DIM_) - mean*mean;
    float rstd = rsqrtf(var + EPS_);
    int b = row / rows_per_batch;
    float* yr = Yout + (size_t)row * DIM_;
#pragma unroll
    for (int i = 0; i < 8; i++) {
        int c = t + 256*i;
        float y = (vbuf[i] - mean) * rstd;
        yr[c] = y * (add_one + scale[b*sstride + c]) + shift[b*hstride + c];
    }
}

// ---------------- RMSNorm (in place) ---------------------------------------
__global__ __launch_bounds__(256) void rms_kernel(float* __restrict__ X,
                                                  const float* __restrict__ w)
{
    int row = blockIdx.x;
    float* xr = X + (size_t)row * DIM_;
    int t = threadIdx.x;
    float s2 = 0.f;
    float vbuf[8];
#pragma unroll
    for (int i = 0; i < 8; i++) {
        float v = xr[t + 256*i];
        vbuf[i] = v;
        s2 += v*v;
    }
    __shared__ float r2[8];
    unsigned lane = t & 31, warp = t >> 5;
#pragma unroll
    for (int o = 16; o; o >>= 1) s2 += __shfl_xor_sync(~0u, s2, o);
    if (lane == 0) r2[warp] = s2;
    __syncthreads();
    if (t == 0) {
        float a = 0.f;
#pragma unroll
        for (int i = 0; i < 8; i++) a += r2[i];
        r2[0] = a;
    }
    __syncthreads();
    float rstd = rsqrtf(r2[0] * (1.0f/DIM_) + EPS_);
#pragma unroll
    for (int i = 0; i < 8; i++) {
        int c = t + 256*i;
        xr[c] = vbuf[i] * rstd * w[c];
    }
}

// ---------------- RoPE (in place, 3D grid pattern) --------------------------
__global__ __launch_bounds__(256) void rope_kernel(float* __restrict__ X,
    const float* __restrict__ fcos, const float* __restrict__ fsin)
{
    int row = blockIdx.x;          // 0..4095
    int s = row & (SEQ_-1);
    int f  = s >> 8;
    int hh = (s >> 4) & 15;
    int ww = s & 15;
    int t = threadIdx.x;
#pragma unroll
    for (int i = 0; i < 4; i++) {
        int p = t + 256*i;         // 0..1023 pair index
        int h = p >> 6;
        int j = p & 63;
        int trow = (j < 22) ? f : (j < 43) ? hh : ww;
        float c  = fcos[trow*64 + j];
        float sn = fsin[trow*64 + j];
        size_t base = (size_t)row * DIM_ + h*HD_ + 2*j;
        float xr = X[base], xi = X[base+1];
        X[base]   = xr*c - xi*sn;
        X[base+1] = xr*sn + xi*c;
    }
}

// ---------------- generic SGEMM: C = epi(A[M,K] @ W[K,N] + bias) ------------
// EPI: 0 = plain, 1 = gelu, 2 = residual:  out = resid + (acc+bias)*scale
template<int EPI>
__global__ __launch_bounds__(256) void gemm_kernel(
    const float* __restrict__ A, const float* __restrict__ W,
    const float* __restrict__ bias,
    const float* __restrict__ resid,
    const float* __restrict__ scale_base, int scale_stride, int rows_per_batch,
    float* __restrict__ C, int M, int N, int K)
{
    __shared__ float As[8][132];
    __shared__ float Bs[8][132];
    int t  = threadIdx.x;
    int tx = t & 15, ty = t >> 4;
    int row0 = blockIdx.y * 128;
    int col0 = blockIdx.x * 128;
    float acc[8][8];
#pragma unroll
    for (int u = 0; u < 8; u++)
#pragma unroll
        for (int v = 0; v < 8; v++) acc[u][v] = 0.f;

    for (int k0 = 0; k0 < K; k0 += 8) {
#pragma unroll
        for (int i = 0; i < 4; i++) {
            int idx = t + 256*i;
            int r = idx >> 3, kk = idx & 7;
            As[kk][r] = A[(size_t)(row0 + r) * K + k0 + kk];
        }
#pragma unroll
        for (int i = 0; i < 4; i++) {
            int idx = t + 256*i;
            int c = idx & 127, kk = idx >> 7;
            Bs[kk][c] = W[(size_t)(k0 + kk) * N + col0 + c];
        }
        __syncthreads();
#pragma unroll
        for (int kk = 0; kk < 8; kk++) {
            float a[8], b[8];
#pragma unroll
            for (int u = 0; u < 8; u++) a[u] = As[kk][ty + 16*u];
#pragma unroll
            for (int v = 0; v < 8; v++) b[v] = Bs[kk][tx + 16*v];
#pragma unroll
            for (int u = 0; u < 8; u++)
#pragma unroll
                for (int v = 0; v < 8; v++)
                    acc[u][v] += a[u] * b[v];
        }
        __syncthreads();
    }

#pragma unroll
    for (int u = 0; u < 8; u++) {
        int r = row0 + ty + 16*u;
#pragma unroll
        for (int v = 0; v < 8; v++) {
            int c = col0 + tx + 16*v;
            float val = acc[u][v] + bias[c];
            if (EPI == 1) {
                val = gelu_tanh(val);
            } else if (EPI == 2) {
                float sc = 1.0f;
                if (scale_base) {
                    int b = r / rows_per_batch;
                    sc = scale_base[b * scale_stride + c];
                }
                val = resid[(size_t)r * N + c] + val * sc;
            }
            C[(size_t)r * N + c] = val;
        }
    }
}

// ---------------- flash attention ------------------------------------------
// Q rows: [b*qlen + s][h*128 + d], KV rows: [b*kvlen + j][h*128 + d]
// block handles 64 queries for one (b,h); online softmax over 64-key tiles.
#define ATTN_SMEM_FLOATS (64*129*2 + 64*65 + 192)
#define ATTN_SMEM_BYTES  (ATTN_SMEM_FLOATS * 4)

__global__ __launch_bounds__(256) void attn_kernel(
    const float* __restrict__ Q, const float* __restrict__ Kb,
    const float* __restrict__ Vb, float* __restrict__ Y,
    int qlen, int kvlen)
{
    extern __shared__ float sm[];
    float* Qs   = sm;                 // 64*129
    float* Ks   = Qs + 64*129;        // 64*129 (reused for V)
    float* Ps   = Ks + 64*129;        // 64*65
    float* mrow = Ps + 64*65;         // 64
    float* lrow = mrow + 64;          // 64
    float* arow = lrow + 64;          // 64

    const float SCALE = 0.08838834764831845f;  // 1/sqrt(128)

    int bh = blockIdx.y;
    int b = bh >> 4, h = bh & 15;
    int qrow0  = b * qlen + blockIdx.x * 64;
    int kvrow0 = b * kvlen;
    int t = threadIdx.x;
    int tx = t & 15, ty = t >> 4;

    // load Q tile
#pragma unroll 4
    for (int i = 0; i < 32; i++) {
        int idx = t + 256*i;
        int r = idx >> 7, c = idx & 127;
        Qs[r*129 + c] = Q[(size_t)(qrow0 + r) * DIM_ + h*HD_ + c];
    }
    if (t < 64) { mrow[t] = -1e30f; lrow[t] = 0.f; }

    float o[4][8];
#pragma unroll
    for (int u = 0; u < 4; u++)
#pragma unroll
        for (int w = 0; w < 8; w++) o[u][w] = 0.f;
    __syncthreads();

    for (int j0 = 0; j0 < kvlen; j0 += 64) {
        // load K tile
#pragma unroll 4
        for (int i = 0; i < 32; i++) {
            int idx = t + 256*i;
            int r = idx >> 7, c = idx & 127;
            Ks[r*129 + c] = Kb[(size_t)(kvrow0 + j0 + r) * DIM_ + h*HD_ + c];
        }
        __syncthreads();

        // S = Q K^T (rows ty+16u, cols tx+16v)
        float s[4][4];
#pragma unroll
        for (int u = 0; u < 4; u++)
#pragma unroll
            for (int v = 0; v < 4; v++) s[u][v] = 0.f;
#pragma unroll 4
        for (int d = 0; d < 128; d++) {
            float qv[4], kv[4];
#pragma unroll
            for (int u = 0; u < 4; u++) qv[u] = Qs[(ty + 16*u)*129 + d];
#pragma unroll
            for (int v = 0; v < 4; v++) kv[v] = Ks[(tx + 16*v)*129 + d];
#pragma unroll
            for (int u = 0; u < 4; u++)
#pragma unroll
                for (int v = 0; v < 4; v++)
                    s[u][v] += qv[u] * kv[v];
        }
#pragma unroll
        for (int u = 0; u < 4; u++)
#pragma unroll
            for (int v = 0; v < 4; v++)
                Ps[(ty + 16*u)*65 + tx + 16*v] = s[u][v] * SCALE;
        __syncthreads();

        // online softmax per row (threads 0..63)
        if (t < 64) {
            float m_old = mrow[t];
            float mn = m_old;
#pragma unroll 8
            for (int j = 0; j < 64; j++) mn = fmaxf(mn, Ps[t*65 + j]);
            float al = __expf(m_old - mn);
            float sum = 0.f;
#pragma unroll 8
            for (int j = 0; j < 64; j++) {
                float p = __expf(Ps[t*65 + j] - mn);
                Ps[t*65 + j] = p;
                sum += p;
            }
            lrow[t] = lrow[t]*al + sum;
            mrow[t] = mn;
            arow[t] = al;
        }
        __syncthreads();

        // rescale accumulators; load V into Ks
#pragma unroll
        for (int u = 0; u < 4; u++) {
            float al = arow[ty + 16*u];
#pragma unroll
            for (int w = 0; w < 8; w++) o[u][w] *= al;
        }
#pragma unroll 4
        for (int i = 0; i < 32; i++) {
            int idx = t + 256*i;
            int r = idx >> 7, c = idx & 127;
            Ks[r*129 + c] = Vb[(size_t)(kvrow0 + j0 + r) * DIM_ + h*HD_ + c];
        }
        __syncthreads();

        // O += P V
#pragma unroll 2
        for (int j = 0; j < 64; j++) {
            float pv[4];
#pragma unroll
            for (int u = 0; u < 4; u++) pv[u] = Ps[(ty + 16*u)*65 + j];
            float vv[8];
#pragma unroll
            for (int w = 0; w < 8; w++) vv[w] = Ks[j*129 + tx + 16*w];
#pragma unroll
            for (int u = 0; u < 4; u++)
#pragma unroll
                for (int w = 0; w < 8; w++)
                    o[u][w] += pv[u] * vv[w];
        }
        __syncthreads();
    }

#pragma unroll
    for (int u = 0; u < 4; u++) {
        float inv = 1.0f / lrow[ty + 16*u];
        int r = qrow0 + ty + 16*u;
#pragma unroll
        for (int w = 0; w < 8; w++) {
            Y[(size_t)r * DIM_ + h*HD_ + tx + 16*w] = o[u][w] * inv;
        }
    }
}

// ---------------- host orchestration ---------------------------------------
extern "C" void kernel_launch(void* const* d_in, const int* in_sizes, int n_in,
                              void* d_out, int out_size)
{
    const float* x        = (const float*)d_in[0];
    const float* e        = (const float*)d_in[1];
    const float* context  = (const float*)d_in[2];
    const float* fcos     = (const float*)d_in[3];
    const float* fsin     = (const float*)d_in[4];
    const float* mod      = (const float*)d_in[5];
    const float* sa_wq    = (const float*)d_in[6];
    const float* sa_bq    = (const float*)d_in[7];
    const float* sa_wk    = (const float*)d_in[8];
    const float* sa_bk    = (const float*)d_in[9];
    const float* sa_wv    = (const float*)d_in[10];
    const float* sa_bv    = (const float*)d_in[11];
    const float* sa_wo    = (const float*)d_in[12];
    const float* sa_bo    = (const float*)d_in[13];
    const float* sa_nq    = (const float*)d_in[14];
    const float* sa_nk    = (const float*)d_in[15];
    const float* ca_wq    = (const float*)d_in[16];
    const float* ca_bq    = (const float*)d_in[17];
    const float* ca_wk    = (const float*)d_in[18];
    const float* ca_bk    = (const float*)d_in[19];
    const float* ca_wv    = (const float*)d_in[20];
    const float* ca_bv    = (const float*)d_in[21];
    const float* ca_wo    = (const float*)d_in[22];
    const float* ca_bo    = (const float*)d_in[23];
    const float* ca_nq    = (const float*)d_in[24];
    const float* ca_nk    = (const float*)d_in[25];
    const float* norm3_w  = (const float*)d_in[26];
    const float* norm3_b  = (const float*)d_in[27];
    const float* ffn_w1   = (const float*)d_in[28];
    const float* ffn_b1   = (const float*)d_in[29];
    const float* ffn_w2   = (const float*)d_in[30];
    const float* ffn_b2   = (const float*)d_in[31];
    float* out = (float*)d_out;

    float *xn, *q, *k, *v, *y, *ck, *cv, *hbuf, *em;
    cudaGetSymbolAddress((void**)&xn,   g_xn);
    cudaGetSymbolAddress((void**)&q,    g_q);
    cudaGetSymbolAddress((void**)&k,    g_k);
    cudaGetSymbolAddress((void**)&v,    g_v);
    cudaGetSymbolAddress((void**)&y,    g_y);
    cudaGetSymbolAddress((void**)&ck,   g_ck);
    cudaGetSymbolAddress((void**)&cv,   g_cv);
    cudaGetSymbolAddress((void**)&hbuf, g_h);
    cudaGetSymbolAddress((void**)&em,   g_em);

    cudaFuncSetAttribute(attn_kernel, cudaFuncAttributeMaxDynamicSharedMemorySize,
                         ATTN_SMEM_BYTES);

    // running residual x lives in d_out
    cudaMemcpyAsync(out, x, sizeof(float)*(size_t)NROWS*DIM_, cudaMemcpyDeviceToDevice);

    // em = modulation + e
    em_kernel<<<(BAT_*6*DIM_ + 255)/256, 256>>>(e, mod);

    // xn = ln(x)*(1+e1)+e0
    ln_kernel<<<NROWS, 256>>>(out, xn, em + 1*DIM_, 6*DIM_, em + 0*DIM_, 6*DIM_, 1.0f, SEQ_);

    dim3 gS(DIM_/128, NROWS/128);     // 16 x 32
    gemm_kernel<0><<<gS, 256>>>(xn, sa_wq, sa_bq, nullptr, nullptr, 0, 0, q, NROWS, DIM_, DIM_);
    gemm_kernel<0><<<gS, 256>>>(xn, sa_wk, sa_bk, nullptr, nullptr, 0, 0, k, NROWS, DIM_, DIM_);
    gemm_kernel<0><<<gS, 256>>>(xn, sa_wv, sa_bv, nullptr, nullptr, 0, 0, v, NROWS, DIM_, DIM_);

    rms_kernel<<<NROWS, 256>>>(q, sa_nq);
    rms_kernel<<<NROWS, 256>>>(k, sa_nk);
    rope_kernel<<<NROWS, 256>>>(q, fcos, fsin);
    rope_kernel<<<NROWS, 256>>>(k, fcos, fsin);

    attn_kernel<<<dim3(SEQ_/64, BAT_*HEADS_), 256, ATTN_SMEM_BYTES>>>(q, k, v, y, SEQ_, SEQ_);

    // x += (y @ wo + bo) * e2
    gemm_kernel<2><<<gS, 256>>>(y, sa_wo, sa_bo, out, em + 2*DIM_, 6*DIM_, SEQ_,
                                out, NROWS, DIM_, DIM_);

    // xn3 = ln(x)*w + b
    ln_kernel<<<NROWS, 256>>>(out, xn, norm3_w, 0, norm3_b, 0, 0.0f, SEQ_);

    gemm_kernel<0><<<gS, 256>>>(xn, ca_wq, ca_bq, nullptr, nullptr, 0, 0, q, NROWS, DIM_, DIM_);
    rms_kernel<<<NROWS, 256>>>(q, ca_nq);

    dim3 gC(DIM_/128, CROWS/128);     // 16 x 8
    gemm_kernel<0><<<gC, 256>>>(context, ca_wk, ca_bk, nullptr, nullptr, 0, 0, ck, CROWS, DIM_, DIM_);
    rms_kernel<<<CROWS, 256>>>(ck, ca_nk);
    gemm_kernel<0><<<gC, 256>>>(context, ca_wv, ca_bv, nullptr, nullptr, 0, 0, cv, CROWS, DIM_, DIM_);

    attn_kernel<<<dim3(SEQ_/64, BAT_*HEADS_), 256, ATTN_SMEM_BYTES>>>(q, ck, cv, y, SEQ_, CTX_);

    // x += y @ ca_wo + bo
    gemm_kernel<2><<<gS, 256>>>(y, ca_wo, ca_bo, out, nullptr, 0, SEQ_,
                                out, NROWS, DIM_, DIM_);

    // xn2 = ln(x)*(1+e4)+e3
    ln_kernel<<<NROWS, 256>>>(out, xn, em + 4*DIM_, 6*DIM_, em + 3*DIM_, 6*DIM_, 1.0f, SEQ_);

    // FFN
    dim3 gF1(FFN_/128, NROWS/128);    // 64 x 32
    gemm_kernel<1><<<gF1, 256>>>(xn, ffn_w1, ffn_b1, nullptr, nullptr, 0, 0,
                                 hbuf, NROWS, FFN_, DIM_);
    dim3 gF2(DIM_/128, NROWS/128);    // 16 x 32
    gemm_kernel<2><<<gF2, 256>>>(hbuf, ffn_w2, ffn_b2, out, em + 5*DIM_, 6*DIM_, SEQ_,
                                 out, NROWS, DIM_, FFN_);
}

// round 3
// speedup vs baseline: 4.4937x; 4.4937x over previous
#include <cuda_runtime.h>
#include <cuda_bf16.h>
#include <math.h>
#include <stdint.h>

// Problem constants
#define DIM_  2048
#define SEQ_  2048
#define BAT_  2
#define HEADS_ 16
#define HD_   128
#define CTX_  512
#define FFN_  8192
#define NROWS (BAT_*SEQ_)    // 4096
#define CROWS (BAT_*CTX_)    // 1024
#define EPS_  1e-6f

// ---------------- scratch (static device globals; no allocation) ----------
__device__ float g_xn[NROWS*DIM_];
__device__ float g_q [NROWS*DIM_];
__device__ float g_k [NROWS*DIM_];
__device__ float g_v [NROWS*DIM_];
__device__ float g_y [NROWS*DIM_];
__device__ float g_ck[CROWS*DIM_];
__device__ float g_cv[CROWS*DIM_];
__device__ float g_ctx[CROWS*DIM_];
__device__ float g_h [(size_t)NROWS*FFN_];
__device__ float g_em[BAT_*6*DIM_];
__device__ float g_wt[(size_t)DIM_*FFN_];
__device__ float g_vt[(size_t)NROWS*DIM_];
__device__ float g_cvt[(size_t)CROWS*DIM_];
__device__ float g_p [(size_t)BAT_*HEADS_*SEQ_*SEQ_];

// ---------------- small helpers -------------------------------------------
__device__ __forceinline__ float gelu_tanh(float v) {
    const float c = 0.7978845608028654f;
    float t = c * (v + 0.044715f * v * v * v);
    return 0.5f * v * (1.0f + tanhf(t));
}

__device__ __forceinline__ float to_tf32(float v) {
    uint32_t u;
    asm("cvt.rna.tf32.f32 %0, %1;" : "=r"(u) : "f"(v));
    return __uint_as_float(u);
}

__device__ __forceinline__ uint32_t smem_u32(const void* p) {
    uint32_t a;
    asm("{ .reg .u64 t; cvta.to.shared.u64 t, %1; cvt.u32.u64 %0, t; }" : "=r"(a) : "l"(p));
    return a;
}

__device__ __forceinline__ void cp_async16(uint32_t dst, const void* src) {
    asm volatile("cp.async.cg.shared.global [%0], [%1], 16;" :: "r"(dst), "l"(src));
}

__device__ __forceinline__ uint32_t lds32(uint32_t addr) {
    uint32_t r;
    asm("ld.shared.b32 %0, [%1];" : "=r"(r) : "r"(addr));
    return r;
}

// ---------------- em = modulation + e --------------------------------------
__global__ void em_kernel(const float* __restrict__ e, const float* __restrict__ mod) {
    int i = blockIdx.x * 256 + threadIdx.x;
    if (i < BAT_*6*DIM_) g_em[i] = e[i] + mod[i % (6*DIM_)];
}

// ---------------- round-copy (tf32 quantize inputs) ------------------------
__global__ void round_copy_kernel(const float* __restrict__ S_, float* __restrict__ D_, int n) {
    int i = blockIdx.x * 256 + threadIdx.x;
    if (i < n) D_[i] = to_tf32(S_[i]);
}

// ---------------- LayerNorm (modulated / affine), tf32-rounded output ------
__global__ __launch_bounds__(256) void ln_kernel(
    const float* __restrict__ X, float* __restrict__ Yout,
    const float* __restrict__ scale, int sstride,
    const float* __restrict__ shift, int hstride,
    float add_one, int rows_per_batch)
{
    int row = blockIdx.x;
    const float* xr = X + (size_t)row * DIM_;
    int t = threadIdx.x;
    float s = 0.f, s2 = 0.f;
    float vbuf[8];
#pragma unroll
    for (int i = 0; i < 8; i++) {
        float v = xr[t + 256*i];
        vbuf[i] = v;
        s += v; s2 += v*v;
    }
    __shared__ float r1[8], r2[8];
    unsigned lane = t & 31, warp = t >> 5;
#pragma unroll
    for (int o = 16; o; o >>= 1) {
        s  += __shfl_xor_sync(~0u, s,  o);
        s2 += __shfl_xor_sync(~0u, s2, o);
    }
    if (lane == 0) { r1[warp] = s; r2[warp] = s2; }
    __syncthreads();
    if (t == 0) {
        float a = 0.f, b = 0.f;
#pragma unroll
        for (int i = 0; i < 8; i++) { a += r1[i]; b += r2[i]; }
        r1[0] = a; r2[0] = b;
    }
    __syncthreads();
    float mean = r1[0] * (1.0f/DIM_);
    float var  = r2[0] * (1.0f/DIM_) - mean*mean;
    float rstd = rsqrtf(var + EPS_);
    int b = row / rows_per_batch;
    float* yr = Yout + (size_t)row * DIM_;
#pragma unroll
    for (int i = 0; i < 8; i++) {
        int c = t + 256*i;
        float y = (vbuf[i] - mean) * rstd;
        yr[c] = to_tf32(y * (add_one + scale[b*sstride + c]) + shift[b*hstride + c]);
    }
}

// ---------------- RMSNorm (in place), tf32-rounded --------------------------
__global__ __launch_bounds__(256) void rms_kernel(float* __restrict__ X,
                                                  const float* __restrict__ w)
{
    int row = blockIdx.x;
    float* xr = X + (size_t)row * DIM_;
    int t = threadIdx.x;
    float s2 = 0.f;
    float vbuf[8];
#pragma unroll
    for (int i = 0; i < 8; i++) {
        float v = xr[t + 256*i];
        vbuf[i] = v;
        s2 += v*v;
    }
    __shared__ float r2[8];
    unsigned lane = t & 31, warp = t >> 5;
#pragma unroll
    for (int o = 16; o; o >>= 1) s2 += __shfl_xor_sync(~0u, s2, o);
    if (lane == 0) r2[warp] = s2;
    __syncthreads();
    if (t == 0) {
        float a = 0.f;
#pragma unroll
        for (int i = 0; i < 8; i++) a += r2[i];
        r2[0] = a;
    }
    __syncthreads();
    float rstd = rsqrtf(r2[0] * (1.0f/DIM_) + EPS_);
#pragma unroll
    for (int i = 0; i < 8; i++) {
        int c = t + 256*i;
        xr[c] = to_tf32(vbuf[i] * rstd * w[c]);
    }
}

// ---------------- RoPE (in place), tf32-rounded ------------------------------
__global__ __launch_bounds__(256) void rope_kernel(float* __restrict__ X,
    const float* __restrict__ fcos, const float* __restrict__ fsin)
{
    int row = blockIdx.x;
    int s = row & (SEQ_-1);
    int f  = s >> 8;
    int hh = (s >> 4) & 15;
    int ww = s & 15;
    int t = threadIdx.x;
#pragma unroll
    for (int i = 0; i < 4; i++) {
        int p = t + 256*i;
        int h = p >> 6;
        int j = p & 63;
        int trow = (j < 22) ? f : (j < 43) ? hh : ww;
        float c  = fcos[trow*64 + j];
        float sn = fsin[trow*64 + j];
        size_t base = (size_t)row * DIM_ + h*HD_ + 2*j;
        float xr = X[base], xi = X[base+1];
        X[base]   = to_tf32(xr*c - xi*sn);
        X[base+1] = to_tf32(xr*sn + xi*c);
    }
}

// ---------------- weight transpose: D[c][r] = S[r][c], tf32-rounded ---------
__global__ __launch_bounds__(256) void transpose_kernel(
    const float* __restrict__ S_, float* __restrict__ D_, int R, int Cc)
{
    __shared__ float tile[32][33];
    int tx = threadIdx.x & 31, ty = threadIdx.x >> 5;
    long long c0 = (long long)blockIdx.x*32, r0 = (long long)blockIdx.y*32;
#pragma unroll
    for (int j = 0; j < 4; j++)
        tile[ty+8*j][tx] = S_[(r0+ty+8*j)*Cc + c0+tx];
    __syncthreads();
#pragma unroll
    for (int j = 0; j < 4; j++)
        D_[(c0+ty+8*j)*R + r0+tx] = to_tf32(tile[tx][ty+8*j]);
}

// ---------------- per-head V transpose: VT[bh][d][j] = V[b][j][h*128+d] -----
__global__ __launch_bounds__(256) void vtrans_kernel(
    const float* __restrict__ V, float* __restrict__ VT, int kv)
{
    __shared__ float tile[32][33];
    int tx = threadIdx.x & 31, ty = threadIdx.x >> 5;
    int bh = blockIdx.z, b = bh >> 4, h = bh & 15;
    long long j0 = (long long)blockIdx.x*32;
    int d0 = blockIdx.y*32;
#pragma unroll
    for (int j = 0; j < 4; j++)
        tile[ty+8*j][tx] = V[((long long)b*kv + j0+ty+8*j)*DIM_ + h*HD_ + d0+tx];
    __syncthreads();
#pragma unroll
    for (int j = 0; j < 4; j++)
        VT[((long long)bh*HD_ + d0+ty+8*j)*kv + j0+tx] = to_tf32(tile[tx][ty+8*j]);
}

// ---------------- softmax over rows of P, tf32-rounded output ---------------
__global__ __launch_bounds__(256) void softmax_kernel(float* __restrict__ P, int cols) {
    size_t row = blockIdx.x;
    float* pr = P + row * (size_t)cols;
    int t = threadIdx.x;
    int per = cols >> 8;       // 8 (2048) or 2 (512)
    float v[8];
    float mx = -1e30f;
    for (int i = 0; i < per; i++) { v[i] = pr[t + (i<<8)]; mx = fmaxf(mx, v[i]); }
    __shared__ float rr[8];
    int lane = t & 31, warp = t >> 5;
#pragma unroll
    for (int o = 16; o; o >>= 1) mx = fmaxf(mx, __shfl_xor_sync(~0u, mx, o));
    if (lane == 0) rr[warp] = mx;
    __syncthreads();
    float m8 = rr[0];
#pragma unroll
    for (int i = 1; i < 8; i++) m8 = fmaxf(m8, rr[i]);
    float sum = 0.f;
    for (int i = 0; i < per; i++) { float e = __expf(v[i] - m8); v[i] = e; sum += e; }
#pragma unroll
    for (int o = 16; o; o >>= 1) sum += __shfl_xor_sync(~0u, sum, o);
    __syncthreads();
    if (lane == 0) rr[warp] = sum;
    __syncthreads();
    float s8 = 0.f;
#pragma unroll
    for (int i = 0; i < 8; i++) s8 += rr[i];
    float inv = 1.0f / s8;
    for (int i = 0; i < per; i++) pr[t + (i<<8)] = to_tf32(v[i] * inv);
}

// ---------------- mma.sync tf32 GEMM ----------------------------------------
// C[M,N] = A[M,K] @ B[N,K]^T  (A K-major rows, B K-major rows = pre-transposed W)
// 128x128 block tile, BK=32, 256 threads = 8 warps (2x4), warp tile 64x32,
// mma.sync.m16n8k8.tf32, cp.async double-buffered, XOR-swizzled smem.
#define GEMM_SMEM (2*2*16384)   // 65536 B: 2 stages x (A 16KB + B 16KB)

__global__ void __launch_bounds__(256) gemm_mma(
    const float* __restrict__ A, long long lda, long long aB, long long aH,
    const float* __restrict__ Bm, long long ldb, long long bB, long long bH,
    float* __restrict__ C, long long ldc, long long cB, long long cH,
    int K,
    const float* __restrict__ bias,
    const float* __restrict__ resid,
    const float* __restrict__ scale, int sstride, int rows_per_batch,
    float scale_const, int mode)
{
    extern __shared__ char smc[];
    uint32_t smb = smem_u32(smc);
    int t = threadIdx.x;
    int lane = t & 31, wid = t >> 5;
    int wm = (wid & 1) * 64;       // warp row offset in tile
    int wn = (wid >> 1) * 32;      // warp col offset in tile
    int g  = lane >> 2;            // group id 0..7
    int w4 = lane & 3;             // id in group 0..3

    int z = blockIdx.z, zb = z >> 4, zh = z & 15;
    A  += (long long)zb*aB + (long long)zh*aH;
    Bm += (long long)zb*bB + (long long)zh*bH;
    long long coff = (long long)zb*cB + (long long)zh*cH;
    C += coff;
    if (resid) resid += coff;
    long long row0 = (long long)blockIdx.y * 128;
    long long col0 = (long long)blockIdx.x * 128;

    float acc[4][4][4];
#pragma unroll
    for (int mf = 0; mf < 4; mf++)
#pragma unroll
        for (int nf = 0; nf < 4; nf++)
#pragma unroll
            for (int i = 0; i < 4; i++) acc[mf][nf][i] = 0.f;

    int KT = K >> 5;

    auto load_tile = [&](int kt, int s) {
        long long k0 = (long long)kt * 32;
        const float* Ab = A + row0*lda + k0;
        const float* Bb = Bm + col0*ldb + k0;
        uint32_t sa = smb + (uint32_t)s*32768u;
        uint32_t sb = sa + 16384u;
#pragma unroll
        for (int i = 0; i < 4; i++) {
            int idx = t + 256*i; int r = idx >> 3, c = idx & 7;
            uint32_t off = (uint32_t)(r*128 + ((c ^ (r & 7)) << 4));
            cp_async16(sa + off, Ab + (long long)r*lda + c*4);
        }
#pragma unroll
        for (int i = 0; i < 4; i++) {
            int idx = t + 256*i; int r = idx >> 3, c = idx & 7;
            uint32_t off = (uint32_t)(r*128 + ((c ^ (r & 7)) << 4));
            cp_async16(sb + off, Bb + (long long)r*ldb + c*4);
        }
        asm volatile("cp.async.commit_group;" ::: "memory");
    };

    load_tile(0, 0);
    if (KT > 1) load_tile(1, 1);

    for (int kt = 0; kt < KT; kt++) {
        int s = kt & 1;
        if (kt + 1 < KT) asm volatile("cp.async.wait_group 1;" ::: "memory");
        else             asm volatile("cp.async.wait_group 0;" ::: "memory");
        __syncthreads();
        uint32_t sa = smb + (uint32_t)s*32768u;
        uint32_t sb = sa + 16384u;

#pragma unroll
        for (int ks = 0; ks < 4; ks++) {
            int e = ks * 2;                       // 16B-chunk index of k0=ks*8
            uint32_t a[4][4], b[4][2];
#pragma unroll
            for (int mf = 0; mf < 4; mf++) {
                int r = wm + mf*16 + g;           // r&7 == g
                uint32_t b0 = sa + (uint32_t)(r*128 + w4*4);
                uint32_t b1 = sa + (uint32_t)((r+8)*128 + w4*4);
                uint32_t x0 = (uint32_t)(((e    ) ^ g) << 4);
                uint32_t x1 = (uint32_t)(((e + 1) ^ g) << 4);
                a[mf][0] = lds32(b0 + x0);
                a[mf][1] = lds32(b1 + x0);
                a[mf][2] = lds32(b0 + x1);
                a[mf][3] = lds32(b1 + x1);
            }
#pragma unroll
            for (int nf = 0; nf < 4; nf++) {
                int r = wn + nf*8 + g;            // r&7 == g
                uint32_t bb = sb + (uint32_t)(r*128 + w4*4);
                uint32_t x0 = (uint32_t)(((e    ) ^ g) << 4);
                uint32_t x1 = (uint32_t)(((e + 1) ^ g) << 4);
                b[nf][0] = lds32(bb + x0);
                b[nf][1] = lds32(bb + x1);
            }
#pragma unroll
            for (int mf = 0; mf < 4; mf++)
#pragma unroll
                for (int nf = 0; nf < 4; nf++) {
                    asm volatile(
                        "mma.sync.aligned.m16n8k8.row.col.f32.tf32.tf32.f32 "
                        "{%0,%1,%2,%3}, {%4,%5,%6,%7}, {%8,%9}, {%0,%1,%2,%3};"
                        : "+f"(acc[mf][nf][0]), "+f"(acc[mf][nf][1]),
                          "+f"(acc[mf][nf][2]), "+f"(acc[mf][nf][3])
                        : "r"(a[mf][0]), "r"(a[mf][1]), "r"(a[mf][2]), "r"(a[mf][3]),
                          "r"(b[nf][0]), "r"(b[nf][1]));
                }
        }
        __syncthreads();
        if (kt + 2 < KT) load_tile(kt + 2, s);
    }

    // epilogue
#pragma unroll
    for (int mf = 0; mf < 4; mf++) {
        long long rb = row0 + wm + mf*16 + g;
#pragma unroll
        for (int half = 0; half < 2; half++) {
            long long r = rb + half*8;
            int bsel = (int)(r / rows_per_batch);
#pragma unroll
            for (int nf = 0; nf < 4; nf++) {
                long long c = col0 + wn + nf*8 + w4*2;
                float v0 = acc[mf][nf][half*2 + 0];
                float v1 = acc[mf][nf][half*2 + 1];
                if (mode == 3) {
                    v0 = to_tf32(v0 * scale_const);
                    v1 = to_tf32(v1 * scale_const);
                } else if (mode == 0) {
                    float bi0 = bias ? bias[c]   : 0.f;
                    float bi1 = bias ? bias[c+1] : 0.f;
                    v0 = to_tf32(v0 + bi0);
                    v1 = to_tf32(v1 + bi1);
                } else if (mode == 1) {
                    v0 = to_tf32(gelu_tanh(v0 + bias[c]));
                    v1 = to_tf32(gelu_tanh(v1 + bias[c+1]));
                } else {
                    float sc0 = scale ? scale[bsel*sstride + c]   : 1.f;
                    float sc1 = scale ? scale[bsel*sstride + c+1] : 1.f;
                    v0 = resid[r*ldc + c]   + (v0 + bias[c])   * sc0;
                    v1 = resid[r*ldc + c+1] + (v1 + bias[c+1]) * sc1;
                }
                C[r*ldc + c]   = v0;
                C[r*ldc + c+1] = v1;
            }
        }
    }
}

// ---------------- host orchestration ---------------------------------------
static void launch_gemm(dim3 grid,
    const float* A, long long lda, long long aB, long long aH,
    const float* Bm, long long ldb, long long bB, long long bH,
    float* C, long long ldc, long long cB, long long cH, int K,
    const float* bias, const float* resid,
    const float* scale, int sstr, int rpb, float sconst, int mode)
{
    gemm_mma<<<grid, 256, GEMM_SMEM>>>(A, lda, aB, aH, Bm, ldb, bB, bH,
                                       C, ldc, cB, cH, K, bias, resid,
                                       scale, sstr, rpb, sconst, mode);
}

extern "C" void kernel_launch(void* const* d_in, const int* in_sizes, int n_in,
                              void* d_out, int out_size)
{
    const float* x        = (const float*)d_in[0];
    const float* e        = (const float*)d_in[1];
    const float* context  = (const float*)d_in[2];
    const float* fcos     = (const float*)d_in[3];
    const float* fsin     = (const float*)d_in[4];
    const float* mod      = (const float*)d_in[5];
    const float* sa_wq    = (const float*)d_in[6];
    const float* sa_bq    = (const float*)d_in[7];
    const float* sa_wk    = (const float*)d_in[8];
    const float* sa_bk    = (const float*)d_in[9];
    const float* sa_wv    = (const float*)d_in[10];
    const float* sa_bv    = (const float*)d_in[11];
    const float* sa_wo    = (const float*)d_in[12];
    const float* sa_bo    = (const float*)d_in[13];
    const float* sa_nq    = (const float*)d_in[14];
    const float* sa_nk    = (const float*)d_in[15];
    const float* ca_wq    = (const float*)d_in[16];
    const float* ca_bq    = (const float*)d_in[17];
    const float* ca_wk    = (const float*)d_in[18];
    const float* ca_bk    = (const float*)d_in[19];
    const float* ca_wv    = (const float*)d_in[20];
    const float* ca_bv    = (const float*)d_in[21];
    const float* ca_wo    = (const float*)d_in[22];
    const float* ca_bo    = (const float*)d_in[23];
    const float* ca_nq    = (const float*)d_in[24];
    const float* ca_nk    = (const float*)d_in[25];
    const float* norm3_w  = (const float*)d_in[26];
    const float* norm3_b  = (const float*)d_in[27];
    const float* ffn_w1   = (const float*)d_in[28];
    const float* ffn_b1   = (const float*)d_in[29];
    const float* ffn_w2   = (const float*)d_in[30];
    const float* ffn_b2   = (const float*)d_in[31];
    float* out = (float*)d_out;

    float *xn, *q, *k, *v, *y, *ck, *cv, *ctx, *hbuf, *em, *wt, *vt, *cvt, *p;
    cudaGetSymbolAddress((void**)&xn,   g_xn);
    cudaGetSymbolAddress((void**)&q,    g_q);
    cudaGetSymbolAddress((void**)&k,    g_k);
    cudaGetSymbolAddress((void**)&v,    g_v);
    cudaGetSymbolAddress((void**)&y,    g_y);
    cudaGetSymbolAddress((void**)&ck,   g_ck);
    cudaGetSymbolAddress((void**)&cv,   g_cv);
    cudaGetSymbolAddress((void**)&ctx,  g_ctx);
    cudaGetSymbolAddress((void**)&hbuf, g_h);
    cudaGetSymbolAddress((void**)&em,   g_em);
    cudaGetSymbolAddress((void**)&wt,   g_wt);
    cudaGetSymbolAddress((void**)&vt,   g_vt);
    cudaGetSymbolAddress((void**)&cvt,  g_cvt);
    cudaGetSymbolAddress((void**)&p,    g_p);

    cudaFuncSetAttribute(gemm_mma, cudaFuncAttributeMaxDynamicSharedMemorySize, GEMM_SMEM);

    const long long SD  = (long long)SEQ_ * DIM_;
    const long long SS  = (long long)SEQ_ * SEQ_;
    const long long SC  = (long long)SEQ_ * CTX_;
    const float QKSCALE = 0.08838834764831845f;   // 1/sqrt(128)

    // residual x lives in d_out
    cudaMemcpyAsync(out, x, sizeof(float)*(size_t)NROWS*DIM_, cudaMemcpyDeviceToDevice);

    em_kernel<<<(BAT_*6*DIM_ + 255)/256, 256>>>(e, mod);
    round_copy_kernel<<<(CROWS*DIM_ + 255)/256, 256>>>(context, ctx, CROWS*DIM_);

    // xn = ln(x)*(1+e1)+e0
    ln_kernel<<<NROWS, 256>>>(out, xn, em + 1*DIM_, 6*DIM_, em + 0*DIM_, 6*DIM_, 1.0f, SEQ_);

    dim3 gT(64, 64), gS(16, 32, 1);
    // SA projections
    transpose_kernel<<<gT, 256>>>(sa_wq, wt, DIM_, DIM_);
    launch_gemm(gS, xn,DIM_,0,0, wt,DIM_,0,0, q,DIM_,0,0, DIM_, sa_bq, nullptr, nullptr,0, NROWS, 0.f, 0);
    transpose_kernel<<<gT, 256>>>(sa_wk, wt, DIM_, DIM_);
    launch_gemm(gS, xn,DIM_,0,0, wt,DIM_,0,0, k,DIM_,0,0, DIM_, sa_bk, nullptr, nullptr,0, NROWS, 0.f, 0);
    transpose_kernel<<<gT, 256>>>(sa_wv, wt, DIM_, DIM_);
    launch_gemm(gS, xn,DIM_,0,0, wt,DIM_,0,0, v,DIM_,0,0, DIM_, sa_bv, nullptr, nullptr,0, NROWS, 0.f, 0);

    rms_kernel<<<NROWS, 256>>>(q, sa_nq);
    rms_kernel<<<NROWS, 256>>>(k, sa_nk);
    rope_kernel<<<NROWS, 256>>>(q, fcos, fsin);
    rope_kernel<<<NROWS, 256>>>(k, fcos, fsin);

    vtrans_kernel<<<dim3(SEQ_/32, 4, 32), 256>>>(v, vt, SEQ_);

    // SA attention: P = scale * Q K^T ; softmax ; Y = P V
    launch_gemm(dim3(16,16,32), q,DIM_, SD,128, k,DIM_, SD,128,
                p, SEQ_, 16*SS, SS, HD_, nullptr, nullptr, nullptr,0, NROWS, QKSCALE, 3);
    softmax_kernel<<<BAT_*HEADS_*SEQ_, 256>>>(p, SEQ_);
    launch_gemm(dim3(1,16,32), p,SEQ_, 16*SS, SS, vt,SEQ_, 16*(long long)HD_*SEQ_, (long long)HD_*SEQ_,
                y, DIM_, SD, 128, SEQ_, nullptr, nullptr, nullptr,0, NROWS, 0.f, 0);

    // x += (y @ sa_wo + bo) * e2
    transpose_kernel<<<gT, 256>>>(sa_wo, wt, DIM_, DIM_);
    launch_gemm(gS, y,DIM_,0,0, wt,DIM_,0,0, out,DIM_,0,0, DIM_, sa_bo, out, em + 2*DIM_, 6*DIM_, SEQ_, 0.f, 2);

    // xn3 = ln(x)*w + b
    ln_kernel<<<NROWS, 256>>>(out, xn, norm3_w, 0, norm3_b, 0, 0.0f, SEQ_);

    transpose_kernel<<<gT, 256>>>(ca_wq, wt, DIM_, DIM_);
    launch_gemm(gS, xn,DIM_,0,0, wt,DIM_,0,0, q,DIM_,0,0, DIM_, ca_bq, nullptr, nullptr,0, NROWS, 0.f, 0);
    rms_kernel<<<NROWS, 256>>>(q, ca_nq);

    dim3 gC(16, 8, 1);
    transpose_kernel<<<gT, 256>>>(ca_wk, wt, DIM_, DIM_);
    launch_gemm(gC, ctx,DIM_,0,0, wt,DIM_,0,0, ck,DIM_,0,0, DIM_, ca_bk, nullptr, nullptr,0, CROWS, 0.f, 0);
    rms_kernel<<<CROWS, 256>>>(ck, ca_nk);
    transpose_kernel<<<gT, 256>>>(ca_wv, wt, DIM_, DIM_);
    launch_gemm(gC, ctx,DIM_,0,0, wt,DIM_,0,0, cv,DIM_,0,0, DIM_, ca_bv, nullptr, nullptr,0, CROWS, 0.f, 0);

    vtrans_kernel<<<dim3(CTX_/32, 4, 32), 256>>>(cv, cvt, CTX_);

    // CA attention
    launch_gemm(dim3(4,16,32), q,DIM_, SD,128, ck,DIM_, (long long)CTX_*DIM_,128,
                p, CTX_, 16*SC, SC, HD_, nullptr, nullptr, nullptr,0, NROWS, QKSCALE, 3);
    softmax_kernel<<<BAT_*HEADS_*SEQ_, 256>>>(p, CTX_);
    launch_gemm(dim3(1,16,32), p,CTX_, 16*SC, SC, cvt,CTX_, 16*(long long)HD_*CTX_, (long long)HD_*CTX_,
                y, DIM_, SD, 128, CTX_, nullptr, nullptr, nullptr,0, NROWS, 0.f, 0);

    // x += y @ ca_wo + bo
    transpose_kernel<<<gT, 256>>>(ca_wo, wt, DIM_, DIM_);
    launch_gemm(gS, y,DIM_,0,0, wt,DIM_,0,0, out,DIM_,0,0, DIM_, ca_bo, out, nullptr, 0, SEQ_, 0.f, 2);

    // xn2 = ln(x)*(1+e4)+e3
    ln_kernel<<<NROWS, 256>>>(out, xn, em + 4*DIM_, 6*DIM_, em + 3*DIM_, 6*DIM_, 1.0f, SEQ_);

    // FFN
    transpose_kernel<<<dim3(FFN_/32, DIM_/32), 256>>>(ffn_w1, wt, DIM_, FFN_);
    launch_gemm(dim3(64,32,1), xn,DIM_,0,0, wt,DIM_,0,0, hbuf,FFN_,0,0, DIM_,
                ffn_b1, nullptr, nullptr,0, NROWS, 0.f, 1);
    transpose_kernel<<<dim3(DIM_/32, FFN_/32), 256>>>(ffn_w2, wt, FFN_, DIM_);
    launch_gemm(gS, hbuf,FFN_,0,0, wt,FFN_,0,0, out,DIM_,0,0, FFN_,
                ffn_b2, out, em + 5*DIM_, 6*DIM_, SEQ_, 0.f, 2);
}

// round 5
// speedup vs baseline: 4.9707x; 1.1062x over previous
#include <cuda_runtime.h>
#include <cuda_bf16.h>
#include <math.h>
#include <stdint.h>

// Problem constants
#define DIM_  2048
#define SEQ_  2048
#define BAT_  2
#define HEADS_ 16
#define HD_   128
#define CTX_  512
#define FFN_  8192
#define NROWS (BAT_*SEQ_)    // 4096
#define CROWS (BAT_*CTX_)    // 1024
#define EPS_  1e-6f

// ---------------- scratch (static device globals; no allocation) ----------
__device__ float g_xn[NROWS*DIM_];
__device__ float g_q [NROWS*DIM_];
__device__ float g_k [NROWS*DIM_];
__device__ float g_v [NROWS*DIM_];
__device__ float g_y [NROWS*DIM_];
__device__ float g_ck[CROWS*DIM_];
__device__ float g_cv[CROWS*DIM_];
__device__ float g_ctx[CROWS*DIM_];
__device__ float g_h [(size_t)NROWS*FFN_];
__device__ float g_em[BAT_*6*DIM_];
__device__ float g_wt[(size_t)DIM_*FFN_];

// ---------------- small helpers -------------------------------------------
__device__ __forceinline__ float gelu_tanh(float v) {
    const float c = 0.7978845608028654f;
    float t = c * (v + 0.044715f * v * v * v);
    return 0.5f * v * (1.0f + tanhf(t));
}

__device__ __forceinline__ float to_tf32(float v) {
    uint32_t u;
    asm("cvt.rna.tf32.f32 %0, %1;" : "=r"(u) : "f"(v));
    return __uint_as_float(u);
}

__device__ __forceinline__ uint32_t smem_u32(const void* p) {
    uint32_t a;
    asm("{ .reg .u64 t; cvta.to.shared.u64 t, %1; cvt.u32.u64 %0, t; }" : "=r"(a) : "l"(p));
    return a;
}

__device__ __forceinline__ void cp_async16(uint32_t dst, const void* src) {
    asm volatile("cp.async.cg.shared.global [%0], [%1], 16;" :: "r"(dst), "l"(src));
}

__device__ __forceinline__ uint32_t lds32(uint32_t addr) {
    uint32_t r;
    asm("ld.shared.b32 %0, [%1];" : "=r"(r) : "r"(addr));
    return r;
}

__device__ __forceinline__ void mma8(float* c, const uint32_t* a, uint32_t b0, uint32_t b1) {
    asm volatile("mma.sync.aligned.m16n8k8.row.col.f32.tf32.tf32.f32 "
        "{%0,%1,%2,%3}, {%4,%5,%6,%7}, {%8,%9}, {%0,%1,%2,%3};"
        : "+f"(c[0]), "+f"(c[1]), "+f"(c[2]), "+f"(c[3])
        : "r"(a[0]), "r"(a[1]), "r"(a[2]), "r"(a[3]), "r"(b0), "r"(b1));
}

// ---------------- em = modulation + e --------------------------------------
__global__ void em_kernel(const float* __restrict__ e, const float* __restrict__ mod) {
    int i = blockIdx.x * 256 + threadIdx.x;
    if (i < BAT_*6*DIM_) g_em[i] = e[i] + mod[i % (6*DIM_)];
}

// ---------------- round-copy (tf32 quantize inputs) ------------------------
__global__ void round_copy_kernel(const float* __restrict__ S_, float* __restrict__ D_, int n) {
    int i = blockIdx.x * 256 + threadIdx.x;
    if (i < n) D_[i] = to_tf32(S_[i]);
}

// ---------------- LayerNorm (modulated / affine), tf32-rounded output ------
__global__ __launch_bounds__(256) void ln_kernel(
    const float* __restrict__ X, float* __restrict__ Yout,
    const float* __restrict__ scale, int sstride,
    const float* __restrict__ shift, int hstride,
    float add_one, int rows_per_batch)
{
    int row = blockIdx.x;
    const float* xr = X + (size_t)row * DIM_;
    int t = threadIdx.x;
    float s = 0.f, s2 = 0.f;
    float vbuf[8];
#pragma unroll
    for (int i = 0; i < 8; i++) {
        float v = xr[t + 256*i];
        vbuf[i] = v;
        s += v; s2 += v*v;
    }
    __shared__ float r1[8], r2[8];
    unsigned lane = t & 31, warp = t >> 5;
#pragma unroll
    for (int o = 16; o; o >>= 1) {
        s  += __shfl_xor_sync(~0u, s,  o);
        s2 += __shfl_xor_sync(~0u, s2, o);
    }
    if (lane == 0) { r1[warp] = s; r2[warp] = s2; }
    __syncthreads();
    if (t == 0) {
        float a = 0.f, b = 0.f;
#pragma unroll
        for (int i = 0; i < 8; i++) { a += r1[i]; b += r2[i]; }
        r1[0] = a; r2[0] = b;
    }
    __syncthreads();
    float mean = r1[0] * (1.0f/DIM_);
    float var  = r2[0] * (1.0f/DIM_) - mean*mean;
    float rstd = rsqrtf(var + EPS_);
    int b = row / rows_per_batch;
    float* yr = Yout + (size_t)row * DIM_;
#pragma unroll
    for (int i = 0; i < 8; i++) {
        int c = t + 256*i;
        float y = (vbuf[i] - mean) * rstd;
        yr[c] = to_tf32(y * (add_one + scale[b*sstride + c]) + shift[b*hstride + c]);
    }
}

// ---------------- RMSNorm (in place), tf32-rounded --------------------------
__global__ __launch_bounds__(256) void rms_kernel(float* __restrict__ X,
                                                  const float* __restrict__ w)
{
    int row = blockIdx.x;
    float* xr = X + (size_t)row * DIM_;
    int t = threadIdx.x;
    float s2 = 0.f;
    float vbuf[8];
#pragma unroll
    for (int i = 0; i < 8; i++) {
        float v = xr[t + 256*i];
        vbuf[i] = v;
        s2 += v*v;
    }
    __shared__ float r2[8];
    unsigned lane = t & 31, warp = t >> 5;
#pragma unroll
    for (int o = 16; o; o >>= 1) s2 += __shfl_xor_sync(~0u, s2, o);
    if (lane == 0) r2[warp] = s2;
    __syncthreads();
    if (t == 0) {
        float a = 0.f;
#pragma unroll
        for (int i = 0; i < 8; i++) a += r2[i];
        r2[0] = a;
    }
    __syncthreads();
    float rstd = rsqrtf(r2[0] * (1.0f/DIM_) + EPS_);
#pragma unroll
    for (int i = 0; i < 8; i++) {
        int c = t + 256*i;
        xr[c] = to_tf32(vbuf[i] * rstd * w[c]);
    }
}

// ---------------- RoPE (in place), tf32-rounded ------------------------------
__global__ __launch_bounds__(256) void rope_kernel(float* __restrict__ X,
    const float* __restrict__ fcos, const float* __restrict__ fsin)
{
    int row = blockIdx.x;
    int s = row & (SEQ_-1);
    int f  = s >> 8;
    int hh = (s >> 4) & 15;
    int ww = s & 15;
    int t = threadIdx.x;
#pragma unroll
    for (int i = 0; i < 4; i++) {
        int p = t + 256*i;
        int h = p >> 6;
        int j = p & 63;
        int trow = (j < 22) ? f : (j < 43) ? hh : ww;
        float c  = fcos[trow*64 + j];
        float sn = fsin[trow*64 + j];
        size_t base = (size_t)row * DIM_ + h*HD_ + 2*j;
        float xr = X[base], xi = X[base+1];
        X[base]   = to_tf32(xr*c - xi*sn);
        X[base+1] = to_tf32(xr*sn + xi*c);
    }
}

// ---------------- weight transpose: D[c][r] = S[r][c], tf32-rounded ---------
__global__ __launch_bounds__(256) void transpose_kernel(
    const float* __restrict__ S_, float* __restrict__ D_, int R, int Cc)
{
    __shared__ float tile[32][33];
    int tx = threadIdx.x & 31, ty = threadIdx.x >> 5;
    long long c0 = (long long)blockIdx.x*32, r0 = (long long)blockIdx.y*32;
#pragma unroll
    for (int j = 0; j < 4; j++)
        tile[ty+8*j][tx] = S_[(r0+ty+8*j)*Cc + c0+tx];
    __syncthreads();
#pragma unroll
    for (int j = 0; j < 4; j++)
        D_[(c0+ty+8*j)*R + r0+tx] = to_tf32(tile[tx][ty+8*j]);
}

// ---------------- mma.sync tf32 GEMM ----------------------------------------
// C[M,N] = A[M,K] @ B[N,K]^T  (A K-major rows, B K-major rows = pre-transposed W)
#define GEMM_SMEM (2*2*16384)

__global__ void __launch_bounds__(256) gemm_mma(
    const float* __restrict__ A, long long lda, long long aB, long long aH,
    const float* __restrict__ Bm, long long ldb, long long bB, long long bH,
    float* __restrict__ C, long long ldc, long long cB, long long cH,
    int K,
    const float* __restrict__ bias,
    const float* __restrict__ resid,
    const float* __restrict__ scale, int sstride, int rows_per_batch,
    float scale_const, int mode)
{
    extern __shared__ char smc[];
    uint32_t smb = smem_u32(smc);
    int t = threadIdx.x;
    int lane = t & 31, wid = t >> 5;
    int wm = (wid & 1) * 64;
    int wn = (wid >> 1) * 32;
    int g  = lane >> 2;
    int w4 = lane & 3;

    int z = blockIdx.z, zb = z >> 4, zh = z & 15;
    A  += (long long)zb*aB + (long long)zh*aH;
    Bm += (long long)zb*bB + (long long)zh*bH;
    long long coff = (long long)zb*cB + (long long)zh*cH;
    C += coff;
    if (resid) resid += coff;
    long long row0 = (long long)blockIdx.y * 128;
    long long col0 = (long long)blockIdx.x * 128;

    float acc[4][4][4];
#pragma unroll
    for (int mf = 0; mf < 4; mf++)
#pragma unroll
        for (int nf = 0; nf < 4; nf++)
#pragma unroll
            for (int i = 0; i < 4; i++) acc[mf][nf][i] = 0.f;

    int KT = K >> 5;

    auto load_tile = [&](int kt, int s) {
        long long k0 = (long long)kt * 32;
        const float* Ab = A + row0*lda + k0;
        const float* Bb = Bm + col0*ldb + k0;
        uint32_t sa = smb + (uint32_t)s*32768u;
        uint32_t sb = sa + 16384u;
#pragma unroll
        for (int i = 0; i < 4; i++) {
            int idx = t + 256*i; int r = idx >> 3, c = idx & 7;
            uint32_t off = (uint32_t)(r*128 + ((c ^ (r & 7)) << 4));
            cp_async16(sa + off, Ab + (long long)r*lda + c*4);
        }
#pragma unroll
        for (int i = 0; i < 4; i++) {
            int idx = t + 256*i; int r = idx >> 3, c = idx & 7;
            uint32_t off = (uint32_t)(r*128 + ((c ^ (r & 7)) << 4));
            cp_async16(sb + off, Bb + (long long)r*ldb + c*4);
        }
        asm volatile("cp.async.commit_group;" ::: "memory");
    };

    load_tile(0, 0);
    if (KT > 1) load_tile(1, 1);

    for (int kt = 0; kt < KT; kt++) {
        int s = kt & 1;
        if (kt + 1 < KT) asm volatile("cp.async.wait_group 1;" ::: "memory");
        else             asm volatile("cp.async.wait_group 0;" ::: "memory");
        __syncthreads();
        uint32_t sa = smb + (uint32_t)s*32768u;
        uint32_t sb = sa + 16384u;

#pragma unroll
        for (int ks = 0; ks < 4; ks++) {
            int e = ks * 2;
            uint32_t a[4][4], b[4][2];
#pragma unroll
            for (int mf = 0; mf < 4; mf++) {
                int r = wm + mf*16 + g;
                uint32_t b0 = sa + (uint32_t)(r*128 + w4*4);
                uint32_t b1 = sa + (uint32_t)((r+8)*128 + w4*4);
                uint32_t x0 = (uint32_t)(((e    ) ^ g) << 4);
                uint32_t x1 = (uint32_t)(((e + 1) ^ g) << 4);
                a[mf][0] = lds32(b0 + x0);
                a[mf][1] = lds32(b1 + x0);
                a[mf][2] = lds32(b0 + x1);
                a[mf][3] = lds32(b1 + x1);
            }
#pragma unroll
            for (int nf = 0; nf < 4; nf++) {
                int r = wn + nf*8 + g;
                uint32_t bb = sb + (uint32_t)(r*128 + w4*4);
                uint32_t x0 = (uint32_t)(((e    ) ^ g) << 4);
                uint32_t x1 = (uint32_t)(((e + 1) ^ g) << 4);
                b[nf][0] = lds32(bb + x0);
                b[nf][1] = lds32(bb + x1);
            }
#pragma unroll
            for (int mf = 0; mf < 4; mf++)
#pragma unroll
                for (int nf = 0; nf < 4; nf++)
                    mma8(acc[mf][nf], a[mf], b[nf][0], b[nf][1]);
        }
        __syncthreads();
        if (kt + 2 < KT) load_tile(kt + 2, s);
    }

    // epilogue
#pragma unroll
    for (int mf = 0; mf < 4; mf++) {
        long long rb = row0 + wm + mf*16 + g;
#pragma unroll
        for (int half = 0; half < 2; half++) {
            long long r = rb + half*8;
            int bsel = (int)(r / rows_per_batch);
#pragma unroll
            for (int nf = 0; nf < 4; nf++) {
                long long c = col0 + wn + nf*8 + w4*2;
                float v0 = acc[mf][nf][half*2 + 0];
                float v1 = acc[mf][nf][half*2 + 1];
                if (mode == 0) {
                    float bi0 = bias ? bias[c]   : 0.f;
                    float bi1 = bias ? bias[c+1] : 0.f;
                    v0 = to_tf32(v0 + bi0);
                    v1 = to_tf32(v1 + bi1);
                } else if (mode == 1) {
                    v0 = to_tf32(gelu_tanh(v0 + bias[c]));
                    v1 = to_tf32(gelu_tanh(v1 + bias[c+1]));
                } else {
                    float sc0 = scale ? scale[bsel*sstride + c]   : 1.f;
                    float sc1 = scale ? scale[bsel*sstride + c+1] : 1.f;
                    v0 = resid[r*ldc + c]   + (v0 + bias[c])   * sc0;
                    v1 = resid[r*ldc + c+1] + (v1 + bias[c+1]) * sc1;
                }
                C[r*ldc + c]   = v0;
                C[r*ldc + c+1] = v1;
            }
        }
    }
}

// ---------------- fused flash attention (mma.sync tf32) ---------------------
// block: 128 queries x one (b,h). 8 warps, each owns 16 query rows.
// K tile 64x128 in smem (4 swizzled panels of 64x32), V double-buffered [64][136],
// P bounce buffer [128][72]. Online softmax in registers (quad shuffles).
#define FL_KB   0u
#define FL_VB   32768u
#define FL_VSZ  34816u
#define FL_PB   (32768u + 2u*FL_VSZ)          // 102400
#define FL_SMEM (FL_PB + 128u*72u*4u)         // 139264

__global__ void __launch_bounds__(256, 1) flash_kernel(
    const float* __restrict__ Q, const float* __restrict__ Kg,
    const float* __restrict__ Vg, float* __restrict__ Y,
    int qlen, int kvlen)
{
    extern __shared__ char smc[];
    uint32_t smb = smem_u32(smc);
    int t = threadIdx.x, lane = t & 31, wid = t >> 5;
    int g = lane >> 2, w4 = lane & 3;
    int wm = wid * 16;
    int bh = blockIdx.y, b = bh >> 4, h = bh & 15;
    long long q0  = (long long)b * qlen + (long long)blockIdx.x * 128;
    long long kv0 = (long long)b * kvlen;
    const float SCALE = 0.08838834764831845f;   // 1/sqrt(128)

    auto loadK = [&](int j0) {
#pragma unroll
        for (int i = 0; i < 8; i++) {
            int idx = t + 256*i;
            int j = idx >> 5, c32 = idx & 31, p = c32 >> 3, cc = c32 & 7;
            const float* src = Kg + (kv0 + j0 + j)*DIM_ + h*HD_ + p*32 + cc*4;
            cp_async16(smb + FL_KB + (uint32_t)(p*8192 + j*128 + (((cc ^ (j & 7)) << 4))), src);
        }
        asm volatile("cp.async.commit_group;" ::: "memory");
    };
    auto loadV = [&](int j0, int buf) {
        uint32_t vb = smb + FL_VB + (uint32_t)buf * FL_VSZ;
#pragma unroll
        for (int i = 0; i < 8; i++) {
            int idx = t + 256*i;
            int j = idx >> 5, c32 = idx & 31;
            const float* src = Vg + (kv0 + j0 + j)*DIM_ + h*HD_ + c32*4;
            cp_async16(vb + (uint32_t)(j*544 + c32*16), src);
        }
        asm volatile("cp.async.commit_group;" ::: "memory");
    };

    loadK(0);
    loadV(0, 0);

    // Q fragments from gmem (Q already tf32-rounded by producers)
    uint32_t qa[16][4];
    {
        const float* Qr0 = Q + (q0 + wm + g)*DIM_ + h*HD_;
        const float* Qr1 = Qr0 + 8*DIM_;
#pragma unroll
        for (int ks = 0; ks < 16; ks++) {
            qa[ks][0] = __float_as_uint(Qr0[ks*8 + w4]);
            qa[ks][1] = __float_as_uint(Qr1[ks*8 + w4]);
            qa[ks][2] = __float_as_uint(Qr0[ks*8 + 4 + w4]);
            qa[ks][3] = __float_as_uint(Qr1[ks*8 + 4 + w4]);
        }
    }

    float o[16][4];
#pragma unroll
    for (int nf = 0; nf < 16; nf++)
#pragma unroll
        for (int i = 0; i < 4; i++) o[nf][i] = 0.f;
    float m0 = -1e30f, m1 = -1e30f, l0 = 0.f, l1 = 0.f;

    int T = kvlen >> 6;
    for (int tt = 0; tt < T; tt++) {
        asm volatile("cp.async.wait_group 0;" ::: "memory");
        __syncthreads();

        // ---- S = Q K^T over this 64-key tile ----
        float sacc[8][4];
#pragma unroll
        for (int nf = 0; nf < 8; nf++)
#pragma unroll
            for (int i = 0; i < 4; i++) sacc[nf][i] = 0.f;

#pragma unroll
        for (int ks = 0; ks < 16; ks++) {
            int p = ks >> 2;
            int e = (ks & 3) * 2;
#pragma unroll
            for (int nf = 0; nf < 8; nf++) {
                int j = nf*8 + g;
                uint32_t base = smb + FL_KB + (uint32_t)(p*8192 + j*128 + w4*4);
                uint32_t b0 = lds32(base + (uint32_t)(((e    ) ^ (j & 7)) << 4));
                uint32_t b1 = lds32(base + (uint32_t)(((e + 1) ^ (j & 7)) << 4));
                mma8(sacc[nf], qa[ks], b0, b1);
            }
        }
        __syncthreads();               // everyone done reading K
        if (tt + 1 < T) {
            loadK((tt + 1) * 64);
            loadV((tt + 1) * 64, (tt + 1) & 1);
        }

        // ---- online softmax (registers + quad shuffles) ----
        float mn0 = m0, mn1 = m1;
#pragma unroll
        for (int nf = 0; nf < 8; nf++) {
            sacc[nf][0] *= SCALE; sacc[nf][1] *= SCALE;
            sacc[nf][2] *= SCALE; sacc[nf][3] *= SCALE;
            mn0 = fmaxf(mn0, fmaxf(sacc[nf][0], sacc[nf][1]));
            mn1 = fmaxf(mn1, fmaxf(sacc[nf][2], sacc[nf][3]));
        }
        mn0 = fmaxf(mn0, __shfl_xor_sync(~0u, mn0, 1));
        mn0 = fmaxf(mn0, __shfl_xor_sync(~0u, mn0, 2));
        mn1 = fmaxf(mn1, __shfl_xor_sync(~0u, mn1, 1));
        mn1 = fmaxf(mn1, __shfl_xor_sync(~0u, mn1, 2));
        float al0 = __expf(m0 - mn0), al1 = __expf(m1 - mn1);
        m0 = mn0; m1 = mn1;

        float s0 = 0.f, s1 = 0.f;
        char* pbase0 = smc + FL_PB + (wm + g)*288 + 2*w4*4;
        char* pbase1 = pbase0 + 8*288;
#pragma unroll
        for (int nf = 0; nf < 8; nf++) {
            float p0 = __expf(sacc[nf][0] - mn0);
            float p1 = __expf(sacc[nf][1] - mn0);
            float p2 = __expf(sacc[nf][2] - mn1);
            float p3 = __expf(sacc[nf][3] - mn1);
            s0 += p0 + p1; s1 += p2 + p3;
            *(float2*)(pbase0 + nf*32) = make_float2(to_tf32(p0), to_tf32(p1));
            *(float2*)(pbase1 + nf*32) = make_float2(to_tf32(p2), to_tf32(p3));
        }
        s0 += __shfl_xor_sync(~0u, s0, 1);
        s0 += __shfl_xor_sync(~0u, s0, 2);
        s1 += __shfl_xor_sync(~0u, s1, 1);
        s1 += __shfl_xor_sync(~0u, s1, 2);
        l0 = l0*al0 + s0;
        l1 = l1*al1 + s1;
#pragma unroll
        for (int nf = 0; nf < 16; nf++) {
            o[nf][0] *= al0; o[nf][1] *= al0;
            o[nf][2] *= al1; o[nf][3] *= al1;
        }
        __syncwarp();                 // P rows are warp-local

        // ---- load P fragments ----
        uint32_t pa[8][4];
        {
            uint32_t pr0 = smb + FL_PB + (uint32_t)((wm + g)*288 + w4*4);
            uint32_t pr1 = pr0 + 8*288;
#pragma unroll
            for (int ks = 0; ks < 8; ks++) {
                pa[ks][0] = lds32(pr0 + ks*32);
                pa[ks][1] = lds32(pr1 + ks*32);
                pa[ks][2] = lds32(pr0 + ks*32 + 16);
                pa[ks][3] = lds32(pr1 + ks*32 + 16);
            }
        }

        // ---- O += P V ----
        uint32_t vb = smb + FL_VB + (uint32_t)(tt & 1) * FL_VSZ;
#pragma unroll
        for (int nf = 0; nf < 16; nf++) {
            uint32_t cbase = vb + (uint32_t)((nf*8 + g)*4);
#pragma unroll
            for (int ks = 0; ks < 8; ks++) {
                uint32_t b0 = lds32(cbase + (uint32_t)((ks*8     + w4)*544));
                uint32_t b1 = lds32(cbase + (uint32_t)((ks*8 + 4 + w4)*544));
                mma8(o[nf], pa[ks], b0, b1);
            }
        }
        __syncthreads();              // done with V buffer before it's reloaded in 2 tiles
    }

    // ---- epilogue ----
    float inv0 = 1.f / l0, inv1 = 1.f / l1;
    float* y0 = Y + (q0 + wm + g)*DIM_ + h*HD_ + 2*w4;
    float* y1 = y0 + 8*DIM_;
#pragma unroll
    for (int nf = 0; nf < 16; nf++) {
        *(float2*)(y0 + nf*8) = make_float2(to_tf32(o[nf][0]*inv0), to_tf32(o[nf][1]*inv0));
        *(float2*)(y1 + nf*8) = make_float2(to_tf32(o[nf][2]*inv1), to_tf32(o[nf][3]*inv1));
    }
}

// ---------------- host orchestration ---------------------------------------
static void launch_gemm(dim3 grid,
    const float* A, long long lda, long long aB, long long aH,
    const float* Bm, long long ldb, long long bB, long long bH,
    float* C, long long ldc, long long cB, long long cH, int K,
    const float* bias, const float* resid,
    const float* scale, int sstr, int rpb, int mode)
{
    gemm_mma<<<grid, 256, GEMM_SMEM>>>(A, lda, aB, aH, Bm, ldb, bB, bH,
                                       C, ldc, cB, cH, K, bias, resid,
                                       scale, sstr, rpb, 0.f, mode);
}

extern "C" void kernel_launch(void* const* d_in, const int* in_sizes, int n_in,
                              void* d_out, int out_size)
{
    const float* x        = (const float*)d_in[0];
    const float* e        = (const float*)d_in[1];
    const float* context  = (const float*)d_in[2];
    const float* fcos     = (const float*)d_in[3];
    const float* fsin     = (const float*)d_in[4];
    const float* mod      = (const float*)d_in[5];
    const float* sa_wq    = (const float*)d_in[6];
    const float* sa_bq    = (const float*)d_in[7];
    const float* sa_wk    = (const float*)d_in[8];
    const float* sa_bk    = (const float*)d_in[9];
    const float* sa_wv    = (const float*)d_in[10];
    const float* sa_bv    = (const float*)d_in[11];
    const float* sa_wo    = (const float*)d_in[12];
    const float* sa_bo    = (const float*)d_in[13];
    const float* sa_nq    = (const float*)d_in[14];
    const float* sa_nk    = (const float*)d_in[15];
    const float* ca_wq    = (const float*)d_in[16];
    const float* ca_bq    = (const float*)d_in[17];
    const float* ca_wk    = (const float*)d_in[18];
    const float* ca_bk    = (const float*)d_in[19];
    const float* ca_wv    = (const float*)d_in[20];
    const float* ca_bv    = (const float*)d_in[21];
    const float* ca_wo    = (const float*)d_in[22];
    const float* ca_bo    = (const float*)d_in[23];
    const float* ca_nq    = (const float*)d_in[24];
    const float* ca_nk    = (const float*)d_in[25];
    const float* norm3_w  = (const float*)d_in[26];
    const float* norm3_b  = (const float*)d_in[27];
    const float* ffn_w1   = (const float*)d_in[28];
    const float* ffn_b1   = (const float*)d_in[29];
    const float* ffn_w2   = (const float*)d_in[30];
    const float* ffn_b2   = (const float*)d_in[31];
    float* out = (float*)d_out;

    float *xn, *q, *k, *v, *y, *ck, *cv, *ctx, *hbuf, *em, *wt;
    cudaGetSymbolAddress((void**)&xn,   g_xn);
    cudaGetSymbolAddress((void**)&q,    g_q);
    cudaGetSymbolAddress((void**)&k,    g_k);
    cudaGetSymbolAddress((void**)&v,    g_v);
    cudaGetSymbolAddress((void**)&y,    g_y);
    cudaGetSymbolAddress((void**)&ck,   g_ck);
    cudaGetSymbolAddress((void**)&cv,   g_cv);
    cudaGetSymbolAddress((void**)&ctx,  g_ctx);
    cudaGetSymbolAddress((void**)&hbuf, g_h);
    cudaGetSymbolAddress((void**)&em,   g_em);
    cudaGetSymbolAddress((void**)&wt,   g_wt);

    cudaFuncSetAttribute(gemm_mma, cudaFuncAttributeMaxDynamicSharedMemorySize, GEMM_SMEM);
    cudaFuncSetAttribute(flash_kernel, cudaFuncAttributeMaxDynamicSharedMemorySize, FL_SMEM);

    // residual x lives in d_out
    cudaMemcpyAsync(out, x, sizeof(float)*(size_t)NROWS*DIM_, cudaMemcpyDeviceToDevice);

    em_kernel<<<(BAT_*6*DIM_ + 255)/256, 256>>>(e, mod);
    round_copy_kernel<<<(CROWS*DIM_ + 255)/256, 256>>>(context, ctx, CROWS*DIM_);

    // xn = ln(x)*(1+e1)+e0
    ln_kernel<<<NROWS, 256>>>(out, xn, em + 1*DIM_, 6*DIM_, em + 0*DIM_, 6*DIM_, 1.0f, SEQ_);

    dim3 gT(64, 64), gS(16, 32, 1);
    // SA projections
    transpose_kernel<<<gT, 256>>>(sa_wq, wt, DIM_, DIM_);
    launch_gemm(gS, xn,DIM_,0,0, wt,DIM_,0,0, q,DIM_,0,0, DIM_, sa_bq, nullptr, nullptr,0, NROWS, 0);
    transpose_kernel<<<gT, 256>>>(sa_wk, wt, DIM_, DIM_);
    launch_gemm(gS, xn,DIM_,0,0, wt,DIM_,0,0, k,DIM_,0,0, DIM_, sa_bk, nullptr, nullptr,0, NROWS, 0);
    transpose_kernel<<<gT, 256>>>(sa_wv, wt, DIM_, DIM_);
    launch_gemm(gS, xn,DIM_,0,0, wt,DIM_,0,0, v,DIM_,0,0, DIM_, sa_bv, nullptr, nullptr,0, NROWS, 0);

    rms_kernel<<<NROWS, 256>>>(q, sa_nq);
    rms_kernel<<<NROWS, 256>>>(k, sa_nk);
    rope_kernel<<<NROWS, 256>>>(q, fcos, fsin);
    rope_kernel<<<NROWS, 256>>>(k, fcos, fsin);

    // fused SA attention
    flash_kernel<<<dim3(SEQ_/128, BAT_*HEADS_), 256, FL_SMEM>>>(q, k, v, y, SEQ_, SEQ_);

    // x += (y @ sa_wo + bo) * e2
    transpose_kernel<<<gT, 256>>>(sa_wo, wt, DIM_, DIM_);
    launch_gemm(gS, y,DIM_,0,0, wt,DIM_,0,0, out,DIM_,0,0, DIM_, sa_bo, out, em + 2*DIM_, 6*DIM_, SEQ_, 2);

    // xn3 = ln(x)*w + b
    ln_kernel<<<NROWS, 256>>>(out, xn, norm3_w, 0, norm3_b, 0, 0.0f, SEQ_);

    transpose_kernel<<<gT, 256>>>(ca_wq, wt, DIM_, DIM_);
    launch_gemm(gS, xn,DIM_,0,0, wt,DIM_,0,0, q,DIM_,0,0, DIM_, ca_bq, nullptr, nullptr,0, NROWS, 0);
    rms_kernel<<<NROWS, 256>>>(q, ca_nq);

    dim3 gC(16, 8, 1);
    transpose_kernel<<<gT, 256>>>(ca_wk, wt, DIM_, DIM_);
    launch_gemm(gC, ctx,DIM_,0,0, wt,DIM_,0,0, ck,DIM_,0,0, DIM_, ca_bk, nullptr, nullptr,0, CROWS, 0);
    rms_kernel<<<CROWS, 256>>>(ck, ca_nk);
    transpose_kernel<<<gT, 256>>>(ca_wv, wt, DIM_, DIM_);
    launch_gemm(gC, ctx,DIM_,0,0, wt,DIM_,0,0, cv,DIM_,0,0, DIM_, ca_bv, nullptr, nullptr,0, CROWS, 0);

    // fused CA attention
    flash_kernel<<<dim3(SEQ_/128, BAT_*HEADS_), 256, FL_SMEM>>>(q, ck, cv, y, SEQ_, CTX_);

    // x += y @ ca_wo + bo
    transpose_kernel<<<gT, 256>>>(ca_wo, wt, DIM_, DIM_);
    launch_gemm(gS, y,DIM_,0,0, wt,DIM_,0,0, out,DIM_,0,0, DIM_, ca_bo, out, nullptr, 0, SEQ_, 2);

    // xn2 = ln(x)*(1+e4)+e3
    ln_kernel<<<NROWS, 256>>>(out, xn, em + 4*DIM_, 6*DIM_, em + 3*DIM_, 6*DIM_, 1.0f, SEQ_);

    // FFN
    transpose_kernel<<<dim3(FFN_/32, DIM_/32), 256>>>(ffn_w1, wt, DIM_, FFN_);
    launch_gemm(dim3(64,32,1), xn,DIM_,0,0, wt,DIM_,0,0, hbuf,FFN_,0,0, DIM_,
                ffn_b1, nullptr, nullptr,0, NROWS, 1);
    transpose_kernel<<<dim3(DIM_/32, FFN_/32), 256>>>(ffn_w2, wt, FFN_, DIM_);
    launch_gemm(gS, hbuf,FFN_,0,0, wt,FFN_,0,0, out,DIM_,0,0, FFN_,
                ffn_b2, out, em + 5*DIM_, 6*DIM_, SEQ_, 2);
}

// round 6
// speedup vs baseline: 9.2925x; 1.8695x over previous
#include <cuda_runtime.h>
#include <cuda_fp16.h>
#include <math.h>
#include <stdint.h>

// Problem constants
#define DIM_  2048
#define SEQ_  2048
#define BAT_  2
#define HEADS_ 16
#define HD_   128
#define CTX_  512
#define FFN_  8192
#define NROWS (BAT_*SEQ_)    // 4096
#define CROWS (BAT_*CTX_)    // 1024
#define EPS_  1e-6f

// ---------------- scratch (static device globals; no allocation) ----------
__device__ __half g_xn[NROWS*DIM_];
__device__ __half g_q [NROWS*DIM_];
__device__ __half g_k [NROWS*DIM_];
__device__ __half g_v [NROWS*DIM_];
__device__ __half g_y [NROWS*DIM_];
__device__ __half g_ck[CROWS*DIM_];
__device__ __half g_cv[CROWS*DIM_];
__device__ __half g_ctx[CROWS*DIM_];
__device__ __half g_h [(size_t)NROWS*FFN_];
__device__ float  g_em[BAT_*6*DIM_];
__device__ __half g_wt[(size_t)DIM_*FFN_];

// ---------------- small helpers -------------------------------------------
__device__ __forceinline__ float gelu_tanh(float v) {
    const float c = 0.7978845608028654f;
    float t = c * (v + 0.044715f * v * v * v);
    return 0.5f * v * (1.0f + tanhf(t));
}

__device__ __forceinline__ uint32_t smem_u32(const void* p) {
    uint32_t a;
    asm("{ .reg .u64 t; cvta.to.shared.u64 t, %1; cvt.u32.u64 %0, t; }" : "=r"(a) : "l"(p));
    return a;
}

__device__ __forceinline__ void cp_async16(uint32_t dst, const void* src) {
    asm volatile("cp.async.cg.shared.global [%0], [%1], 16;" :: "r"(dst), "l"(src));
}

__device__ __forceinline__ uint32_t lds32(uint32_t addr) {
    uint32_t r;
    asm("ld.shared.b32 %0, [%1];" : "=r"(r) : "r"(addr));
    return r;
}

// fp16 MMA: D(16x8,f32) += A(16x16,f16) * B(16x8,f16)^T-ish (row.col)
__device__ __forceinline__ void mma16(float* c, const uint32_t* a, uint32_t b0, uint32_t b1) {
    asm volatile("mma.sync.aligned.m16n8k16.row.col.f32.f16.f16.f32 "
        "{%0,%1,%2,%3}, {%4,%5,%6,%7}, {%8,%9}, {%0,%1,%2,%3};"
        : "+f"(c[0]), "+f"(c[1]), "+f"(c[2]), "+f"(c[3])
        : "r"(a[0]), "r"(a[1]), "r"(a[2]), "r"(a[3]), "r"(b0), "r"(b1));
}

__device__ __forceinline__ void ldsm4t(uint32_t& r0, uint32_t& r1, uint32_t& r2, uint32_t& r3,
                                       uint32_t a) {
    asm volatile("ldmatrix.sync.aligned.m8n8.x4.trans.shared.b16 {%0,%1,%2,%3}, [%4];"
        : "=r"(r0), "=r"(r1), "=r"(r2), "=r"(r3) : "r"(a));
}

// ---------------- em = modulation + e --------------------------------------
__global__ void em_kernel(const float* __restrict__ e, const float* __restrict__ mod) {
    int i = blockIdx.x * 256 + threadIdx.x;
    if (i < BAT_*6*DIM_) g_em[i] = e[i] + mod[i % (6*DIM_)];
}

// ---------------- round-copy to half ---------------------------------------
__global__ void round_copy_kernel(const float* __restrict__ S_, __half* __restrict__ D_, int n) {
    int i = blockIdx.x * 256 + threadIdx.x;
    if (i < n) D_[i] = __float2half_rn(S_[i]);
}

// ---------------- LayerNorm (modulated / affine) -> half --------------------
__global__ __launch_bounds__(256) void ln_kernel(
    const float* __restrict__ X, __half* __restrict__ Yout,
    const float* __restrict__ scale, int sstride,
    const float* __restrict__ shift, int hstride,
    float add_one, int rows_per_batch)
{
    int row = blockIdx.x;
    const float* xr = X + (size_t)row * DIM_;
    int t = threadIdx.x;
    float s = 0.f, s2 = 0.f;
    float vbuf[8];
#pragma unroll
    for (int i = 0; i < 8; i++) {
        float v = xr[t + 256*i];
        vbuf[i] = v;
        s += v; s2 += v*v;
    }
    __shared__ float r1[8], r2[8];
    unsigned lane = t & 31, warp = t >> 5;
#pragma unroll
    for (int o = 16; o; o >>= 1) {
        s  += __shfl_xor_sync(~0u, s,  o);
        s2 += __shfl_xor_sync(~0u, s2, o);
    }
    if (lane == 0) { r1[warp] = s; r2[warp] = s2; }
    __syncthreads();
    if (t == 0) {
        float a = 0.f, b = 0.f;
#pragma unroll
        for (int i = 0; i < 8; i++) { a += r1[i]; b += r2[i]; }
        r1[0] = a; r2[0] = b;
    }
    __syncthreads();
    float mean = r1[0] * (1.0f/DIM_);
    float var  = r2[0] * (1.0f/DIM_) - mean*mean;
    float rstd = rsqrtf(var + EPS_);
    int b = row / rows_per_batch;
    __half* yr = Yout + (size_t)row * DIM_;
#pragma unroll
    for (int i = 0; i < 8; i++) {
        int c = t + 256*i;
        float y = (vbuf[i] - mean) * rstd;
        yr[c] = __float2half_rn(y * (add_one + scale[b*sstride + c]) + shift[b*hstride + c]);
    }
}

// ---------------- RMSNorm (in place on half) --------------------------------
__global__ __launch_bounds__(256) void rms_kernel(__half* __restrict__ X,
                                                  const float* __restrict__ w)
{
    int row = blockIdx.x;
    __half* xr = X + (size_t)row * DIM_;
    int t = threadIdx.x;
    float s2 = 0.f;
    float vbuf[8];
#pragma unroll
    for (int i = 0; i < 8; i++) {
        float v = __half2float(xr[t + 256*i]);
        vbuf[i] = v;
        s2 += v*v;
    }
    __shared__ float r2[8];
    unsigned lane = t & 31, warp = t >> 5;
#pragma unroll
    for (int o = 16; o; o >>= 1) s2 += __shfl_xor_sync(~0u, s2, o);
    if (lane == 0) r2[warp] = s2;
    __syncthreads();
    if (t == 0) {
        float a = 0.f;
#pragma unroll
        for (int i = 0; i < 8; i++) a += r2[i];
        r2[0] = a;
    }
    __syncthreads();
    float rstd = rsqrtf(r2[0] * (1.0f/DIM_) + EPS_);
#pragma unroll
    for (int i = 0; i < 8; i++) {
        int c = t + 256*i;
        xr[c] = __float2half_rn(vbuf[i] * rstd * w[c]);
    }
}

// ---------------- RoPE (in place on half) ------------------------------------
__global__ __launch_bounds__(256) void rope_kernel(__half* __restrict__ X,
    const float* __restrict__ fcos, const float* __restrict__ fsin)
{
    int row = blockIdx.x;
    int s = row & (SEQ_-1);
    int f  = s >> 8;
    int hh = (s >> 4) & 15;
    int ww = s & 15;
    int t = threadIdx.x;
#pragma unroll
    for (int i = 0; i < 4; i++) {
        int p = t + 256*i;
        int h = p >> 6;
        int j = p & 63;
        int trow = (j < 22) ? f : (j < 43) ? hh : ww;
        float c  = fcos[trow*64 + j];
        float sn = fsin[trow*64 + j];
        size_t base = (size_t)row * DIM_ + h*HD_ + 2*j;
        __half2 xv = *(__half2*)(X + base);
        float xr = __half2float(xv.x), xi = __half2float(xv.y);
        *(__half2*)(X + base) = __floats2half2_rn(xr*c - xi*sn, xr*sn + xi*c);
    }
}

// ---------------- weight transpose: D[c][r] = half(S[r][c]) -----------------
__global__ __launch_bounds__(256) void transpose_kernel(
    const float* __restrict__ S_, __half* __restrict__ D_, int R, int Cc)
{
    __shared__ float tile[32][33];
    int tx = threadIdx.x & 31, ty = threadIdx.x >> 5;
    long long c0 = (long long)blockIdx.x*32, r0 = (long long)blockIdx.y*32;
#pragma unroll
    for (int j = 0; j < 4; j++)
        tile[ty+8*j][tx] = S_[(r0+ty+8*j)*Cc + c0+tx];
    __syncthreads();
#pragma unroll
    for (int j = 0; j < 4; j++)
        D_[(c0+ty+8*j)*R + r0+tx] = __float2half_rn(tile[tx][ty+8*j]);
}

// ---------------- fp16 mma.sync GEMM ----------------------------------------
// C[M,N] = A[M,K] @ B[N,K]^T, half inputs, fp32 accum.
// 128x128 tile, BK=64 halves (128B rows), 8 warps (2x4), warp tile 64x32.
#define GEMM_SMEM (2*2*16384)

__global__ void __launch_bounds__(256) gemm_mma(
    const __half* __restrict__ A, long long lda,
    const __half* __restrict__ Bm, long long ldb,
    __half* __restrict__ Ch, float* __restrict__ Cf, long long ldc,
    int K,
    const float* __restrict__ bias,
    const float* __restrict__ resid,
    const float* __restrict__ scale, int sstride, int rows_per_batch,
    int mode)
{
    extern __shared__ char smc[];
    uint32_t smb = smem_u32(smc);
    int t = threadIdx.x;
    int lane = t & 31, wid = t >> 5;
    int wm = (wid & 1) * 64;
    int wn = (wid >> 1) * 32;
    int g  = lane >> 2;
    int w4 = lane & 3;

    long long row0 = (long long)blockIdx.y * 128;
    long long col0 = (long long)blockIdx.x * 128;

    float acc[4][4][4];
#pragma unroll
    for (int mf = 0; mf < 4; mf++)
#pragma unroll
        for (int nf = 0; nf < 4; nf++)
#pragma unroll
            for (int i = 0; i < 4; i++) acc[mf][nf][i] = 0.f;

    int KT = K >> 6;

    auto load_tile = [&](int kt, int s) {
        long long k0 = (long long)kt * 64;
        const __half* Ab = A + row0*lda + k0;
        const __half* Bb = Bm + col0*ldb + k0;
        uint32_t sa = smb + (uint32_t)s*32768u;
        uint32_t sb = sa + 16384u;
#pragma unroll
        for (int i = 0; i < 4; i++) {
            int idx = t + 256*i; int r = idx >> 3, c = idx & 7;
            uint32_t off = (uint32_t)(r*128 + ((c ^ (r & 7)) << 4));
            cp_async16(sa + off, Ab + (long long)r*lda + c*8);
        }
#pragma unroll
        for (int i = 0; i < 4; i++) {
            int idx = t + 256*i; int r = idx >> 3, c = idx & 7;
            uint32_t off = (uint32_t)(r*128 + ((c ^ (r & 7)) << 4));
            cp_async16(sb + off, Bb + (long long)r*ldb + c*8);
        }
        asm volatile("cp.async.commit_group;" ::: "memory");
    };

    load_tile(0, 0);
    if (KT > 1) load_tile(1, 1);

    for (int kt = 0; kt < KT; kt++) {
        int s = kt & 1;
        if (kt + 1 < KT) asm volatile("cp.async.wait_group 1;" ::: "memory");
        else             asm volatile("cp.async.wait_group 0;" ::: "memory");
        __syncthreads();
        uint32_t sa = smb + (uint32_t)s*32768u;
        uint32_t sb = sa + 16384u;

#pragma unroll
        for (int ks = 0; ks < 4; ks++) {              // 4 k16 steps = K 64
            int e = ks * 2;
            uint32_t a[4][4], b[4][2];
#pragma unroll
            for (int mf = 0; mf < 4; mf++) {
                int r = wm + mf*16 + g;
                uint32_t b0 = sa + (uint32_t)(r*128 + w4*4);
                uint32_t b1 = sa + (uint32_t)((r+8)*128 + w4*4);
                uint32_t x0 = (uint32_t)(((e    ) ^ g) << 4);
                uint32_t x1 = (uint32_t)(((e + 1) ^ g) << 4);
                a[mf][0] = lds32(b0 + x0);
                a[mf][1] = lds32(b1 + x0);
                a[mf][2] = lds32(b0 + x1);
                a[mf][3] = lds32(b1 + x1);
            }
#pragma unroll
            for (int nf = 0; nf < 4; nf++) {
                int r = wn + nf*8 + g;
                uint32_t bb = sb + (uint32_t)(r*128 + w4*4);
                uint32_t x0 = (uint32_t)(((e    ) ^ g) << 4);
                uint32_t x1 = (uint32_t)(((e + 1) ^ g) << 4);
                b[nf][0] = lds32(bb + x0);
                b[nf][1] = lds32(bb + x1);
            }
#pragma unroll
            for (int mf = 0; mf < 4; mf++)
#pragma unroll
                for (int nf = 0; nf < 4; nf++)
                    mma16(acc[mf][nf], a[mf], b[nf][0], b[nf][1]);
        }
        __syncthreads();
        if (kt + 2 < KT) load_tile(kt + 2, s);
    }

    // epilogue
#pragma unroll
    for (int mf = 0; mf < 4; mf++) {
        long long rb = row0 + wm + mf*16 + g;
#pragma unroll
        for (int half_ = 0; half_ < 2; half_++) {
            long long r = rb + half_*8;
            int bsel = (int)(r / rows_per_batch);
#pragma unroll
            for (int nf = 0; nf < 4; nf++) {
                long long c = col0 + wn + nf*8 + w4*2;
                float v0 = acc[mf][nf][half_*2 + 0];
                float v1 = acc[mf][nf][half_*2 + 1];
                if (mode == 0) {
                    v0 += bias[c]; v1 += bias[c+1];
                    *(__half2*)(Ch + r*ldc + c) = __floats2half2_rn(v0, v1);
                } else if (mode == 1) {
                    v0 = gelu_tanh(v0 + bias[c]);
                    v1 = gelu_tanh(v1 + bias[c+1]);
                    *(__half2*)(Ch + r*ldc + c) = __floats2half2_rn(v0, v1);
                } else {
                    float sc0 = scale ? scale[bsel*sstride + c]   : 1.f;
                    float sc1 = scale ? scale[bsel*sstride + c+1] : 1.f;
                    float2 rs = *(const float2*)(resid + r*ldc + c);
                    float2 ov;
                    ov.x = rs.x + (v0 + bias[c])   * sc0;
                    ov.y = rs.y + (v1 + bias[c+1]) * sc1;
                    *(float2*)(Cf + r*ldc + c) = ov;
                }
            }
        }
    }
}

// ---------------- fused flash attention (fp16 mma.sync) ---------------------
// block: 128 queries x one (b,h). 8 warps x 16 query rows.
// K: 2 swizzled panels 64x64 halves (8KB each). V: double buffer [64][272B rows].
// P: [128][144B rows] half. Online softmax in registers.
#define FL_KB   0u
#define FL_VB   16384u
#define FL_VSZ  17408u
#define FL_PB   (16384u + 2u*FL_VSZ)          // 51200
#define FL_SMEM (FL_PB + 128u*144u)           // 69632

__global__ void __launch_bounds__(256, 1) flash_kernel(
    const __half* __restrict__ Q, const __half* __restrict__ Kg,
    const __half* __restrict__ Vg, __half* __restrict__ Y,
    int qlen, int kvlen)
{
    extern __shared__ char smc[];
    uint32_t smb = smem_u32(smc);
    int t = threadIdx.x, lane = t & 31, wid = t >> 5;
    int g = lane >> 2, w4 = lane & 3;
    int wm = wid * 16;
    int bh = blockIdx.y, b = bh >> 4, h = bh & 15;
    long long q0  = (long long)b * qlen + (long long)blockIdx.x * 128;
    long long kv0 = (long long)b * kvlen;
    const float SCALE = 0.08838834764831845f;   // 1/sqrt(128)

    auto loadK = [&](int j0) {
#pragma unroll
        for (int i = 0; i < 4; i++) {
            int idx = t + 256*i;
            int j = idx >> 4, c = idx & 15;
            int p = c >> 3, cc = c & 7;
            const __half* src = Kg + (kv0 + j0 + j)*DIM_ + h*HD_ + c*8;
            cp_async16(smb + FL_KB + (uint32_t)(p*8192 + j*128 + ((cc ^ (j & 7)) << 4)), src);
        }
        asm volatile("cp.async.commit_group;" ::: "memory");
    };
    auto loadV = [&](int j0, int buf) {
        uint32_t vb = smb + FL_VB + (uint32_t)buf * FL_VSZ;
#pragma unroll
        for (int i = 0; i < 4; i++) {
            int idx = t + 256*i;
            int j = idx >> 4, c = idx & 15;
            const __half* src = Vg + (kv0 + j0 + j)*DIM_ + h*HD_ + c*8;
            cp_async16(vb + (uint32_t)(j*272 + c*16), src);
        }
        asm volatile("cp.async.commit_group;" ::: "memory");
    };

    loadK(0);
    loadV(0, 0);

    // Q fragments from gmem (half)
    uint32_t qa[8][4];
    {
        const __half* Qr0 = Q + (q0 + wm + g)*DIM_ + h*HD_;
        const __half* Qr1 = Qr0 + 8*DIM_;
#pragma unroll
        for (int ks = 0; ks < 8; ks++) {
            qa[ks][0] = *(const uint32_t*)(Qr0 + ks*16 + 2*w4);
            qa[ks][1] = *(const uint32_t*)(Qr1 + ks*16 + 2*w4);
            qa[ks][2] = *(const uint32_t*)(Qr0 + ks*16 + 8 + 2*w4);
            qa[ks][3] = *(const uint32_t*)(Qr1 + ks*16 + 8 + 2*w4);
        }
    }

    float o[16][4];
#pragma unroll
    for (int nf = 0; nf < 16; nf++)
#pragma unroll
        for (int i = 0; i < 4; i++) o[nf][i] = 0.f;
    float m0 = -1e30f, m1 = -1e30f, l0 = 0.f, l1 = 0.f;

    int T = kvlen >> 6;
    for (int tt = 0; tt < T; tt++) {
        asm volatile("cp.async.wait_group 0;" ::: "memory");
        __syncthreads();

        // ---- S = Q K^T over 64-key tile (8 k16 steps) ----
        float sacc[8][4];
#pragma unroll
        for (int nf = 0; nf < 8; nf++)
#pragma unroll
            for (int i = 0; i < 4; i++) sacc[nf][i] = 0.f;

#pragma unroll
        for (int ks = 0; ks < 8; ks++) {
            int p = ks >> 2;
            int e = (ks & 3) * 2;
#pragma unroll
            for (int nf = 0; nf < 8; nf++) {
                int j = nf*8 + g;
                uint32_t base = smb + FL_KB + (uint32_t)(p*8192 + j*128 + w4*4);
                uint32_t b0 = lds32(base + (uint32_t)(((e    ) ^ (j & 7)) << 4));
                uint32_t b1 = lds32(base + (uint32_t)(((e + 1) ^ (j & 7)) << 4));
                mma16(sacc[nf], qa[ks], b0, b1);
            }
        }
        __syncthreads();               // everyone done reading K
        if (tt + 1 < T) {
            loadK((tt + 1) * 64);
            loadV((tt + 1) * 64, (tt + 1) & 1);
        }

        // ---- online softmax ----
        float mn0 = m0, mn1 = m1;
#pragma unroll
        for (int nf = 0; nf < 8; nf++) {
            sacc[nf][0] *= SCALE; sacc[nf][1] *= SCALE;
            sacc[nf][2] *= SCALE; sacc[nf][3] *= SCALE;
            mn0 = fmaxf(mn0, fmaxf(sacc[nf][0], sacc[nf][1]));
            mn1 = fmaxf(mn1, fmaxf(sacc[nf][2], sacc[nf][3]));
        }
        mn0 = fmaxf(mn0, __shfl_xor_sync(~0u, mn0, 1));
        mn0 = fmaxf(mn0, __shfl_xor_sync(~0u, mn0, 2));
        mn1 = fmaxf(mn1, __shfl_xor_sync(~0u, mn1, 1));
        mn1 = fmaxf(mn1, __shfl_xor_sync(~0u, mn1, 2));
        float al0 = __expf(m0 - mn0), al1 = __expf(m1 - mn1);
        m0 = mn0; m1 = mn1;

        float s0 = 0.f, s1 = 0.f;
        char* pbase0 = smc + FL_PB + (wm + g)*144 + w4*4;
        char* pbase1 = pbase0 + 8*144;
#pragma unroll
        for (int nf = 0; nf < 8; nf++) {
            float p0 = __expf(sacc[nf][0] - mn0);
            float p1 = __expf(sacc[nf][1] - mn0);
            float p2 = __expf(sacc[nf][2] - mn1);
            float p3 = __expf(sacc[nf][3] - mn1);
            s0 += p0 + p1; s1 += p2 + p3;
            *(__half2*)(pbase0 + nf*16) = __floats2half2_rn(p0, p1);
            *(__half2*)(pbase1 + nf*16) = __floats2half2_rn(p2, p3);
        }
        s0 += __shfl_xor_sync(~0u, s0, 1);
        s0 += __shfl_xor_sync(~0u, s0, 2);
        s1 += __shfl_xor_sync(~0u, s1, 1);
        s1 += __shfl_xor_sync(~0u, s1, 2);
        l0 = l0*al0 + s0;
        l1 = l1*al1 + s1;
#pragma unroll
        for (int nf = 0; nf < 16; nf++) {
            o[nf][0] *= al0; o[nf][1] *= al0;
            o[nf][2] *= al1; o[nf][3] *= al1;
        }
        __syncwarp();                 // P rows are warp-local

        // ---- P fragments (4 k16 steps over 64 keys) ----
        uint32_t pa[4][4];
        {
            uint32_t pr0 = smb + FL_PB + (uint32_t)((wm + g)*144 + w4*4);
            uint32_t pr1 = pr0 + 8*144;
#pragma unroll
            for (int ks = 0; ks < 4; ks++) {
                pa[ks][0] = lds32(pr0 + ks*32);
                pa[ks][1] = lds32(pr1 + ks*32);
                pa[ks][2] = lds32(pr0 + ks*32 + 16);
                pa[ks][3] = lds32(pr1 + ks*32 + 16);
            }
        }

        // ---- O += P V  (V fragments via ldmatrix.x4.trans) ----
        uint32_t vb = smb + FL_VB + (uint32_t)(tt & 1) * FL_VSZ;
        int grp = lane >> 3, rr = lane & 7;
#pragma unroll
        for (int ks = 0; ks < 4; ks++) {
#pragma unroll
            for (int dp = 0; dp < 8; dp++) {
                int j  = ks*16 + (grp & 1)*8 + rr;
                int d0 = dp*16 + (grp >> 1)*8;
                uint32_t addr = vb + (uint32_t)(j*272 + d0*2);
                uint32_t r0, r1, r2, r3;
                ldsm4t(r0, r1, r2, r3, addr);
                mma16(o[dp*2    ], pa[ks], r0, r1);
                mma16(o[dp*2 + 1], pa[ks], r2, r3);
            }
        }
        __syncthreads();              // done with V buffer
    }

    // ---- epilogue ----
    float inv0 = 1.f / l0, inv1 = 1.f / l1;
    __half* y0 = Y + (q0 + wm + g)*DIM_ + h*HD_ + 2*w4;
    __half* y1 = y0 + 8*DIM_;
#pragma unroll
    for (int nf = 0; nf < 16; nf++) {
        *(__half2*)(y0 + nf*8) = __floats2half2_rn(o[nf][0]*inv0, o[nf][1]*inv0);
        *(__half2*)(y1 + nf*8) = __floats2half2_rn(o[nf][2]*inv1, o[nf][3]*inv1);
    }
}

// ---------------- host orchestration ---------------------------------------
static void launch_gemm(dim3 grid,
    const __half* A, long long lda, const __half* Bm, long long ldb,
    __half* Ch, float* Cf, long long ldc, int K,
    const float* bias, const float* resid,
    const float* scale, int sstr, int rpb, int mode)
{
    gemm_mma<<<grid, 256, GEMM_SMEM>>>(A, lda, Bm, ldb, Ch, Cf, ldc, K,
                                       bias, resid, scale, sstr, rpb, mode);
}

extern "C" void kernel_launch(void* const* d_in, const int* in_sizes, int n_in,
                              void* d_out, int out_size)
{
    const float* x        = (const float*)d_in[0];
    const float* e        = (const float*)d_in[1];
    const float* context  = (const float*)d_in[2];
    const float* fcos     = (const float*)d_in[3];
    const float* fsin     = (const float*)d_in[4];
    const float* mod      = (const float*)d_in[5];
    const float* sa_wq    = (const float*)d_in[6];
    const float* sa_bq    = (const float*)d_in[7];
    const float* sa_wk    = (const float*)d_in[8];
    const float* sa_bk    = (const float*)d_in[9];
    const float* sa_wv    = (const float*)d_in[10];
    const float* sa_bv    = (const float*)d_in[11];
    const float* sa_wo    = (const float*)d_in[12];
    const float* sa_bo    = (const float*)d_in[13];
    const float* sa_nq    = (const float*)d_in[14];
    const float* sa_nk    = (const float*)d_in[15];
    const float* ca_wq    = (const float*)d_in[16];
    const float* ca_bq    = (const float*)d_in[17];
    const float* ca_wk    = (const float*)d_in[18];
    const float* ca_bk    = (const float*)d_in[19];
    const float* ca_wv    = (const float*)d_in[20];
    const float* ca_bv    = (const float*)d_in[21];
    const float* ca_wo    = (const float*)d_in[22];
    const float* ca_bo    = (const float*)d_in[23];
    const float* ca_nq    = (const float*)d_in[24];
    const float* ca_nk    = (const float*)d_in[25];
    const float* norm3_w  = (const float*)d_in[26];
    const float* norm3_b  = (const float*)d_in[27];
    const float* ffn_w1   = (const float*)d_in[28];
    const float* ffn_b1   = (const float*)d_in[29];
    const float* ffn_w2   = (const float*)d_in[30];
    const float* ffn_b2   = (const float*)d_in[31];
    float* out = (float*)d_out;

    __half *xn, *q, *k, *v, *y, *ck, *cv, *ctx, *hbuf, *wt;
    float *em;
    cudaGetSymbolAddress((void**)&xn,   g_xn);
    cudaGetSymbolAddress((void**)&q,    g_q);
    cudaGetSymbolAddress((void**)&k,    g_k);
    cudaGetSymbolAddress((void**)&v,    g_v);
    cudaGetSymbolAddress((void**)&y,    g_y);
    cudaGetSymbolAddress((void**)&ck,   g_ck);
    cudaGetSymbolAddress((void**)&cv,   g_cv);
    cudaGetSymbolAddress((void**)&ctx,  g_ctx);
    cudaGetSymbolAddress((void**)&hbuf, g_h);
    cudaGetSymbolAddress((void**)&em,   g_em);
    cudaGetSymbolAddress((void**)&wt,   g_wt);

    cudaFuncSetAttribute(gemm_mma, cudaFuncAttributeMaxDynamicSharedMemorySize, GEMM_SMEM);
    cudaFuncSetAttribute(flash_kernel, cudaFuncAttributeMaxDynamicSharedMemorySize, FL_SMEM);

    // residual x lives in d_out
    cudaMemcpyAsync(out, x, sizeof(float)*(size_t)NROWS*DIM_, cudaMemcpyDeviceToDevice);

    em_kernel<<<(BAT_*6*DIM_ + 255)/256, 256>>>(e, mod);
    round_copy_kernel<<<(CROWS*DIM_ + 255)/256, 256>>>(context, ctx, CROWS*DIM_);

    // xn = ln(x)*(1+e1)+e0
    ln_kernel<<<NROWS, 256>>>(out, xn, em + 1*DIM_, 6*DIM_, em + 0*DIM_, 6*DIM_, 1.0f, SEQ_);

    dim3 gT(64, 64), gS(16, 32);
    // SA projections
    transpose_kernel<<<gT, 256>>>(sa_wq, wt, DIM_, DIM_);
    launch_gemm(gS, xn,DIM_, wt,DIM_, q,nullptr,DIM_, DIM_, sa_bq, nullptr, nullptr,0, NROWS, 0);
    transpose_kernel<<<gT, 256>>>(sa_wk, wt, DIM_, DIM_);
    launch_gemm(gS, xn,DIM_, wt,DIM_, k,nullptr,DIM_, DIM_, sa_bk, nullptr, nullptr,0, NROWS, 0);
    transpose_kernel<<<gT, 256>>>(sa_wv, wt, DIM_, DIM_);
    launch_gemm(gS, xn,DIM_, wt,DIM_, v,nullptr,DIM_, DIM_, sa_bv, nullptr, nullptr,0, NROWS, 0);

    rms_kernel<<<NROWS, 256>>>(q, sa_nq);
    rms_kernel<<<NROWS, 256>>>(k, sa_nk);
    rope_kernel<<<NROWS, 256>>>(q, fcos, fsin);
    rope_kernel<<<NROWS, 256>>>(k, fcos, fsin);

    // fused SA attention
    flash_kernel<<<dim3(SEQ_/128, BAT_*HEADS_), 256, FL_SMEM>>>(q, k, v, y, SEQ_, SEQ_);

    // x += (y @ sa_wo + bo) * e2
    transpose_kernel<<<gT, 256>>>(sa_wo, wt, DIM_, DIM_);
    launch_gemm(gS, y,DIM_, wt,DIM_, nullptr,out,DIM_, DIM_, sa_bo, out, em + 2*DIM_, 6*DIM_, SEQ_, 2);

    // xn3 = ln(x)*w + b
    ln_kernel<<<NROWS, 256>>>(out, xn, norm3_w, 0, norm3_b, 0, 0.0f, SEQ_);

    transpose_kernel<<<gT, 256>>>(ca_wq, wt, DIM_, DIM_);
    launch_gemm(gS, xn,DIM_, wt,DIM_, q,nullptr,DIM_, DIM_, ca_bq, nullptr, nullptr,0, NROWS, 0);
    rms_kernel<<<NROWS, 256>>>(q, ca_nq);

    dim3 gC(16, 8);
    transpose_kernel<<<gT, 256>>>(ca_wk, wt, DIM_, DIM_);
    launch_gemm(gC, ctx,DIM_, wt,DIM_, ck,nullptr,DIM_, DIM_, ca_bk, nullptr, nullptr,0, CROWS, 0);
    rms_kernel<<<CROWS, 256>>>(ck, ca_nk);
    transpose_kernel<<<gT, 256>>>(ca_wv, wt, DIM_, DIM_);
    launch_gemm(gC, ctx,DIM_, wt,DIM_, cv,nullptr,DIM_, DIM_, ca_bv, nullptr, nullptr,0, CROWS, 0);

    // fused CA attention
    flash_kernel<<<dim3(SEQ_/128, BAT_*HEADS_), 256, FL_SMEM>>>(q, ck, cv, y, SEQ_, CTX_);

    // x += y @ ca_wo + bo
    transpose_kernel<<<gT, 256>>>(ca_wo, wt, DIM_, DIM_);
    launch_gemm(gS, y,DIM_, wt,DIM_, nullptr,out,DIM_, DIM_, ca_bo, out, nullptr, 0, SEQ_, 2);

    // xn2 = ln(x)*(1+e4)+e3
    ln_kernel<<<NROWS, 256>>>(out, xn, em + 4*DIM_, 6*DIM_, em + 3*DIM_, 6*DIM_, 1.0f, SEQ_);

    // FFN
    transpose_kernel<<<dim3(FFN_/32, DIM_/32), 256>>>(ffn_w1, wt, DIM_, FFN_);
    launch_gemm(dim3(64,32), xn,DIM_, wt,DIM_, hbuf,nullptr,FFN_, DIM_,
                ffn_b1, nullptr, nullptr,0, NROWS, 1);
    transpose_kernel<<<dim3(DIM_/32, FFN_/32), 256>>>(ffn_w2, wt, FFN_, DIM_);
    launch_gemm(gS, hbuf,FFN_, wt,FFN_, nullptr,out,DIM_, FFN_,
                ffn_b2, out, em + 5*DIM_, 6*DIM_, SEQ_, 2);
}